// round 9
// baseline (speedup 1.0000x reference)
#include <cuda_runtime.h>
#include <math.h>
#include <stdint.h>

#define SEQ 2048
#define HID 2048
#define NH 32
#define NKV 8
#define HD 64
#define KVW (NKV*HD)       /* 512 */
#define QKVW (HID + 2*KVW) /* 3072 */

// ---------------- scratch ------------------------------------------------------
__device__ float g_qkv[SEQ * QKVW];
__device__ float g_att[SEQ * HID];
__device__ float g_hs32[SEQ * HID];
__device__ float g_wqkvT[QKVW * HID];
__device__ float g_woT[HID * HID];

// ================= helpers =================
__device__ __forceinline__ uint32_t smem_u32(const void* p) {
    uint32_t a;
    asm("{ .reg .u64 t; cvta.to.shared.u64 t, %1; cvt.u32.u64 %0, t; }" : "=r"(a) : "l"(p));
    return a;
}
__device__ __forceinline__ uint32_t f2tf32(float f) {
    uint32_t r;
    asm("cvt.rna.tf32.f32 %0, %1;" : "=r"(r) : "f"(f));
    return r;
}
__device__ __forceinline__ float f2tf32f(float f) {
    return __uint_as_float(f2tf32(f));
}
#define CP_ASYNC16(dst, src) \
    asm volatile("cp.async.cg.shared.global [%0], [%1], 16;" :: "r"(dst), "l"(src))
#define CP_COMMIT() asm volatile("cp.async.commit_group;" ::: "memory")
#define CP_WAIT(n)  asm volatile("cp.async.wait_group %0;" :: "n"(n) : "memory")

__device__ __forceinline__ void mma_tf32_16x8x8(float& c0, float& c1, float& c2, float& c3,
                                                uint32_t a0, uint32_t a1, uint32_t a2, uint32_t a3,
                                                uint32_t b0, uint32_t b1) {
    asm volatile(
        "mma.sync.aligned.m16n8k8.row.col.f32.tf32.tf32.f32 "
        "{%0,%1,%2,%3}, {%4,%5,%6,%7}, {%8,%9}, {%0,%1,%2,%3};"
        : "+f"(c0), "+f"(c1), "+f"(c2), "+f"(c3)
        : "r"(a0), "r"(a1), "r"(a2), "r"(a3), "r"(b0), "r"(b1));
}

// ---------------- elementwise tf32-round copy ---------------------------------
__global__ __launch_bounds__(256)
void round_copy(const float* __restrict__ in, float* __restrict__ out)
{
    const int i = (blockIdx.x * 256 + threadIdx.x) * 4;
    float4 v = *(const float4*)(in + i);
    v.x = f2tf32f(v.x); v.y = f2tf32f(v.y);
    v.z = f2tf32f(v.z); v.w = f2tf32f(v.w);
    *(float4*)(out + i) = v;
}

// ---------------- weight transpose + tf32 round -------------------------------
__global__ __launch_bounds__(256)
void transpose32(const float* __restrict__ in, float* __restrict__ out, int K, int N)
{
    __shared__ float t[32][33];
    const int bx = blockIdx.x * 32;
    const int by = blockIdx.y * 32;
    const int tx = threadIdx.x, ty = threadIdx.y;
#pragma unroll
    for (int i = 0; i < 32; i += 8)
        t[ty + i][tx] = in[(size_t)(by + ty + i) * N + bx + tx];
    __syncthreads();
#pragma unroll
    for (int i = 0; i < 32; i += 8)
        out[(size_t)(bx + ty + i) * K + by + tx] = f2tf32f(t[tx][ty + i]);
}

// ---------------- tf32 mma.sync GEMM ------------------------------------------
#define GPAD 36
#define GBUF (128 * GPAD)
#define G_SMEM_BYTES (4 * GBUF * 4)

__global__ __launch_bounds__(256)
void gemm_mma(const float* __restrict__ A, const float* __restrict__ BT,
              float* __restrict__ C, int M, int N, int K, int roundOut)
{
    extern __shared__ float sm[];
    float* sA = sm;
    float* sB = sm + 2 * GBUF;

    const int tid  = threadIdx.x;
    const int wid  = tid >> 5;
    const int lane = tid & 31;
    const int g    = lane >> 2;
    const int tg   = lane & 3;
    const int wm   = (wid & 3) * 32;
    const int wn   = (wid >> 2) * 64;
    const int m0 = blockIdx.y * 128;
    const int n0 = blockIdx.x * 128;

    const int lrow  = tid >> 1;
    const int lcol  = (tid & 1) * 16;
    const float* gA = A  + (size_t)(m0 + lrow) * K + lcol;
    const float* gB = BT + (size_t)(n0 + lrow) * K + lcol;
    const uint32_t sbase = smem_u32(sm);
    const uint32_t sArow = sbase + (uint32_t)(lrow * GPAD + lcol) * 4u;
    const uint32_t sBrow = sArow + 2u * GBUF * 4u;

    float acc[2][8][4];
#pragma unroll
    for (int mt = 0; mt < 2; mt++)
#pragma unroll
        for (int nt = 0; nt < 8; nt++)
#pragma unroll
            for (int i = 0; i < 4; i++) acc[mt][nt][i] = 0.f;

    const int nch = K >> 5;
    {
#pragma unroll
        for (int j = 0; j < 4; j++) {
            CP_ASYNC16(sArow + j * 16u, gA + j * 4);
            CP_ASYNC16(sBrow + j * 16u, gB + j * 4);
        }
        CP_COMMIT();
    }

    for (int c = 0; c < nch; ++c) {
        const int buf = c & 1;
        if (c + 1 < nch) {
            const uint32_t off = (uint32_t)(((c + 1) & 1) * GBUF) * 4u;
            const float* pa = gA + (c + 1) * 32;
            const float* pb = gB + (c + 1) * 32;
#pragma unroll
            for (int j = 0; j < 4; j++) {
                CP_ASYNC16(sArow + off + j * 16u, pa + j * 4);
                CP_ASYNC16(sBrow + off + j * 16u, pb + j * 4);
            }
            CP_COMMIT();
            CP_WAIT(1);
        } else {
            CP_WAIT(0);
        }
        __syncthreads();

        const float* tA = sA + buf * GBUF;
        const float* tB = sB + buf * GBUF;

#pragma unroll
        for (int ks = 0; ks < 4; ++ks) {
            const int kk = ks * 8 + tg;
            uint32_t af[2][4];
#pragma unroll
            for (int mt = 0; mt < 2; mt++) {
                const int r = wm + mt * 16 + g;
                af[mt][0] = __float_as_uint(tA[r * GPAD + kk]);
                af[mt][1] = __float_as_uint(tA[(r + 8) * GPAD + kk]);
                af[mt][2] = __float_as_uint(tA[r * GPAD + kk + 4]);
                af[mt][3] = __float_as_uint(tA[(r + 8) * GPAD + kk + 4]);
            }
            uint32_t bf[8][2];
#pragma unroll
            for (int nt = 0; nt < 8; nt++) {
                const int r = wn + nt * 8 + g;
                bf[nt][0] = __float_as_uint(tB[r * GPAD + kk]);
                bf[nt][1] = __float_as_uint(tB[r * GPAD + kk + 4]);
            }
#pragma unroll
            for (int mt = 0; mt < 2; mt++)
#pragma unroll
                for (int nt = 0; nt < 8; nt++)
                    mma_tf32_16x8x8(acc[mt][nt][0], acc[mt][nt][1],
                                    acc[mt][nt][2], acc[mt][nt][3],
                                    af[mt][0], af[mt][1], af[mt][2], af[mt][3],
                                    bf[nt][0], bf[nt][1]);
        }
        __syncthreads();
    }

#pragma unroll
    for (int mt = 0; mt < 2; mt++) {
        const int r0 = m0 + wm + mt * 16 + g;
#pragma unroll
        for (int nt = 0; nt < 8; nt++) {
            const int col = n0 + wn + nt * 8 + 2 * tg;
            float2 v0 = make_float2(acc[mt][nt][0], acc[mt][nt][1]);
            float2 v1 = make_float2(acc[mt][nt][2], acc[mt][nt][3]);
            if (roundOut) {
                v0.x = f2tf32f(v0.x); v0.y = f2tf32f(v0.y);
                v1.x = f2tf32f(v1.x); v1.y = f2tf32f(v1.y);
            }
            *(float2*)(C + (size_t)r0 * N + col) = v0;
            *(float2*)(C + (size_t)(r0 + 8) * N + col) = v1;
        }
    }
}

// ---------------- fused per-head RMSNorm + RoPE (rounded, scaled store) -------
__global__ __launch_bounds__(256)
void norm_rope_kernel(float* __restrict__ x, const float* __restrict__ w,
                      const int* __restrict__ pos, int nheads, int rw, float scale)
{
    const int gw = (blockIdx.x * blockDim.x + threadIdx.x) >> 5;
    const int lane = threadIdx.x & 31;
    const int total = SEQ * nheads;
    if (gw >= total) return;
    const int s = gw / nheads;
    const int hh = gw - s * nheads;

    float* p = x + (size_t)s * rw + hh * HD;
    float x0 = p[lane];
    float x1 = p[lane + 32];

    float ss = x0 * x0 + x1 * x1;
#pragma unroll
    for (int o = 16; o; o >>= 1) ss += __shfl_xor_sync(0xffffffffu, ss, o);
    const float inv = rsqrtf(ss * (1.f / 64.f) + 1e-6f);
    x0 *= inv * w[lane];
    x1 *= inv * w[lane + 32];

    const float ang = (float)pos[s] * __expf(-(float)lane * (1.f / 32.f) * 9.2103403719761836f);
    float sn, c;
    sincosf(ang, &sn, &c);
    p[lane]      = f2tf32f((x0 * c - x1 * sn) * scale);
    p[lane + 32] = f2tf32f((x1 * c + x0 * sn) * scale);
}

// ---------------- causal flash attention: cp.async double-buffered KV ---------
// K and V in natural [j][d] layout (pre-rounded tf32 in gmem). LPT ordering.
#define APAD 68
#define KVTILE (64 * APAD)                     /* floats per K or V tile */
#define AT_SMEM_FLOATS (4 * KVTILE + 8 * 16 * APAD)
#define AT_SMEM_BYTES  (AT_SMEM_FLOATS * 4)    /* 104448 B */
#define L2E 1.4426950408889634f

__global__ __launch_bounds__(256)
void attn_mma(const float* __restrict__ qb, const float* __restrict__ kb,
              const float* __restrict__ vb, float* __restrict__ ob,
              int ldq, int ldkv)
{
    extern __shared__ float sm[];
    // layout: [Ks0, Vs0, Ks1, Vs1, Ps]
    float* Ps = sm + 4 * KVTILE;

    const int tid = threadIdx.x;
    const int wid = tid >> 5;
    const int lane = tid & 31;
    const int g = lane >> 2;
    const int tg = lane & 3;
    const int qt = (int)gridDim.x - 1 - (int)blockIdx.x;  // LPT
    const int h = blockIdx.y;
    const int kvh = h >> 2;

    float* Pw = Ps + wid * 16 * APAD;
    uint32_t* Pwu = (uint32_t*)Pw;

    // loader mapping (all threads): row r, 16-float chunk c4
    const int lr = tid >> 2;
    const int lc4 = (tid & 3) * 16;
    const uint32_t sbase = smem_u32(sm);
    const uint32_t sKrow0 = sbase + (uint32_t)(lr * APAD + lc4) * 4u;
    const float* kbase = kb + (size_t)kvh * HD + lc4;
    const float* vbase = vb + (size_t)kvh * HD + lc4;

    // ---- Q fragments (pre-rounded, pre-scaled in gmem) ----
    uint32_t aq[8][4];
    {
        const float* qp = qb + (size_t)(qt * 128 + wid * 16) * ldq + h * HD;
#pragma unroll
        for (int ks = 0; ks < 8; ks++) {
            const int c0 = ks * 8 + tg;
            aq[ks][0] = __float_as_uint(qp[(size_t)g * ldq + c0]);
            aq[ks][1] = __float_as_uint(qp[(size_t)(g + 8) * ldq + c0]);
            aq[ks][2] = __float_as_uint(qp[(size_t)g * ldq + c0 + 4]);
            aq[ks][3] = __float_as_uint(qp[(size_t)(g + 8) * ldq + c0 + 4]);
        }
    }

    float o[8][4];
#pragma unroll
    for (int nt = 0; nt < 8; nt++)
#pragma unroll
        for (int i = 0; i < 4; i++) o[nt][i] = 0.f;
    float m0 = -1e30f, m1 = -1e30f, l0 = 0.f, l1 = 0.f;

    const int r0g = qt * 128 + wid * 16 + g;
    const int r1g = r0g + 8;
    const int nkt = 2 * qt + 2;

    // ---- prefetch tile 0 into buffer 0 ----
    {
        const float* kp = kbase + (size_t)lr * ldkv;
        const float* vp = vbase + (size_t)lr * ldkv;
#pragma unroll
        for (int j = 0; j < 4; j++) {
            CP_ASYNC16(sKrow0 + j * 16u, kp + j * 4);
            CP_ASYNC16(sKrow0 + (uint32_t)KVTILE * 4u + j * 16u, vp + j * 4);
        }
        CP_COMMIT();
    }

    for (int kt = 0; kt < nkt; ++kt) {
        if (kt + 1 < nkt) {
            const uint32_t boff = (uint32_t)(((kt + 1) & 1) * 2 * KVTILE) * 4u;
            const float* kp = kbase + (size_t)((kt + 1) * 64 + lr) * ldkv;
            const float* vp = vbase + (size_t)((kt + 1) * 64 + lr) * ldkv;
#pragma unroll
            for (int j = 0; j < 4; j++) {
                CP_ASYNC16(sKrow0 + boff + j * 16u, kp + j * 4);
                CP_ASYNC16(sKrow0 + boff + (uint32_t)KVTILE * 4u + j * 16u, vp + j * 4);
            }
            CP_COMMIT();
            CP_WAIT(1);
        } else {
            CP_WAIT(0);
        }
        __syncthreads();

        const float* Ks = sm + (kt & 1) * 2 * KVTILE;
        const float* Vs = Ks + KVTILE;

        const bool active = !(kt == 2 * qt + 1 && wid < 4);
        if (active) {
            // ---- S = Q @ K^T ----
            float s[8][4];
#pragma unroll
            for (int nt = 0; nt < 8; nt++)
#pragma unroll
                for (int i = 0; i < 4; i++) s[nt][i] = 0.f;

#pragma unroll
            for (int ks = 0; ks < 8; ks++) {
                const int kk = ks * 8 + tg;
#pragma unroll
                for (int nt = 0; nt < 8; nt++) {
                    const uint32_t b0 = __float_as_uint(Ks[(nt * 8 + g) * APAD + kk]);
                    const uint32_t b1 = __float_as_uint(Ks[(nt * 8 + g) * APAD + kk + 4]);
                    mma_tf32_16x8x8(s[nt][0], s[nt][1], s[nt][2], s[nt][3],
                                    aq[ks][0], aq[ks][1], aq[ks][2], aq[ks][3],
                                    b0, b1);
                }
            }

            // ---- causal mask ----
            if (kt >= 2 * qt) {
#pragma unroll
                for (int nt = 0; nt < 8; nt++) {
                    const int j0 = kt * 64 + nt * 8 + 2 * tg;
                    if (j0 > r0g)     s[nt][0] = -1e30f;
                    if (j0 + 1 > r0g) s[nt][1] = -1e30f;
                    if (j0 > r1g)     s[nt][2] = -1e30f;
                    if (j0 + 1 > r1g) s[nt][3] = -1e30f;
                }
            }

            // ---- online softmax ----
            float mx0 = -1e30f, mx1 = -1e30f;
#pragma unroll
            for (int nt = 0; nt < 8; nt++) {
                mx0 = fmaxf(mx0, fmaxf(s[nt][0], s[nt][1]));
                mx1 = fmaxf(mx1, fmaxf(s[nt][2], s[nt][3]));
            }
            mx0 = fmaxf(mx0, __shfl_xor_sync(0xffffffffu, mx0, 1));
            mx0 = fmaxf(mx0, __shfl_xor_sync(0xffffffffu, mx0, 2));
            mx1 = fmaxf(mx1, __shfl_xor_sync(0xffffffffu, mx1, 1));
            mx1 = fmaxf(mx1, __shfl_xor_sync(0xffffffffu, mx1, 2));

            const float mn0 = fmaxf(m0, mx0);
            const float mn1 = fmaxf(m1, mx1);
            const float al0 = exp2f((m0 - mn0) * L2E);
            const float al1 = exp2f((m1 - mn1) * L2E);
            float sum0 = 0.f, sum1 = 0.f;
#pragma unroll
            for (int nt = 0; nt < 8; nt++) {
                s[nt][0] = exp2f((s[nt][0] - mn0) * L2E);
                s[nt][1] = exp2f((s[nt][1] - mn0) * L2E);
                s[nt][2] = exp2f((s[nt][2] - mn1) * L2E);
                s[nt][3] = exp2f((s[nt][3] - mn1) * L2E);
                sum0 += s[nt][0] + s[nt][1];
                sum1 += s[nt][2] + s[nt][3];
            }
            sum0 += __shfl_xor_sync(0xffffffffu, sum0, 1);
            sum0 += __shfl_xor_sync(0xffffffffu, sum0, 2);
            sum1 += __shfl_xor_sync(0xffffffffu, sum1, 1);
            sum1 += __shfl_xor_sync(0xffffffffu, sum1, 2);
            m0 = mn0; m1 = mn1;
            l0 = l0 * al0 + sum0;
            l1 = l1 * al1 + sum1;
#pragma unroll
            for (int nt = 0; nt < 8; nt++) {
                o[nt][0] *= al0; o[nt][1] *= al0;
                o[nt][2] *= al1; o[nt][3] *= al1;
            }

            // ---- stage P (tf32) per-warp ----
#pragma unroll
            for (int nt = 0; nt < 8; nt++) {
                const int c = nt * 8 + 2 * tg;
                Pwu[g * APAD + c]           = f2tf32(s[nt][0]);
                Pwu[g * APAD + c + 1]       = f2tf32(s[nt][1]);
                Pwu[(g + 8) * APAD + c]     = f2tf32(s[nt][2]);
                Pwu[(g + 8) * APAD + c + 1] = f2tf32(s[nt][3]);
            }
            __syncwarp();

            // ---- O += P @ V (V natural [j][d]; B frag = V[j=kk][d=nt*8+g]) ----
#pragma unroll
            for (int ks = 0; ks < 8; ks++) {
                const int kk = ks * 8 + tg;
                const uint32_t a0 = Pwu[g * APAD + kk];
                const uint32_t a1 = Pwu[(g + 8) * APAD + kk];
                const uint32_t a2 = Pwu[g * APAD + kk + 4];
                const uint32_t a3 = Pwu[(g + 8) * APAD + kk + 4];
#pragma unroll
                for (int nt = 0; nt < 8; nt++) {
                    const uint32_t b0 = __float_as_uint(Vs[kk * APAD + nt * 8 + g]);
                    const uint32_t b1 = __float_as_uint(Vs[(kk + 4) * APAD + nt * 8 + g]);
                    mma_tf32_16x8x8(o[nt][0], o[nt][1], o[nt][2], o[nt][3],
                                    a0, a1, a2, a3, b0, b1);
                }
            }
        }
        __syncthreads();
    }

    // ---- epilogue: tf32-round (feeds O-proj A operand) ----
    const float il0 = 1.f / l0;
    const float il1 = 1.f / l1;
#pragma unroll
    for (int nt = 0; nt < 8; nt++) {
        const int col = h * HD + nt * 8 + 2 * tg;
        *(float2*)(ob + (size_t)r0g * HID + col) =
            make_float2(f2tf32f(o[nt][0] * il0), f2tf32f(o[nt][1] * il0));
        *(float2*)(ob + (size_t)r1g * HID + col) =
            make_float2(f2tf32f(o[nt][2] * il1), f2tf32f(o[nt][3] * il1));
    }
}

// ---------------- launch ------------------------------------------------------
extern "C" void kernel_launch(void* const* d_in, const int* in_sizes, int n_in,
                              void* d_out, int out_size)
{
    const float* hs  = (const float*)d_in[0];
    const int*   pos = (const int*)  d_in[1];
    const float* wq  = (const float*)d_in[2];
    const float* wk  = (const float*)d_in[3];
    const float* wv  = (const float*)d_in[4];
    const float* wo  = (const float*)d_in[5];
    const float* qw  = (const float*)d_in[6];
    const float* kw  = (const float*)d_in[7];
    float* out = (float*)d_out;

    float *pqkv, *pa, *phs, *pwqkvT, *pwoT;
    cudaGetSymbolAddress((void**)&pqkv, g_qkv);
    cudaGetSymbolAddress((void**)&pa, g_att);
    cudaGetSymbolAddress((void**)&phs, g_hs32);
    cudaGetSymbolAddress((void**)&pwqkvT, g_wqkvT);
    cudaGetSymbolAddress((void**)&pwoT, g_woT);

    cudaFuncSetAttribute(gemm_mma, cudaFuncAttributeMaxDynamicSharedMemorySize,
                         G_SMEM_BYTES);
    cudaFuncSetAttribute(attn_mma, cudaFuncAttributeMaxDynamicSharedMemorySize,
                         AT_SMEM_BYTES);

    dim3 tb(32, 8);
    round_copy<<<(SEQ * HID) / 1024, 256>>>(hs, phs);
    transpose32<<<dim3(HID / 32, HID / 32), tb>>>(wq, pwqkvT, HID, HID);
    transpose32<<<dim3(KVW / 32, HID / 32), tb>>>(wk, pwqkvT + (size_t)HID * HID, HID, KVW);
    transpose32<<<dim3(KVW / 32, HID / 32), tb>>>(wv, pwqkvT + (size_t)(HID + KVW) * HID, HID, KVW);
    transpose32<<<dim3(HID / 32, HID / 32), tb>>>(wo, pwoT, HID, HID);

    // fused QKV projection, output rounded to tf32 (V consumed as-is by attn)
    gemm_mma<<<dim3(QKVW / 128, SEQ / 128), 256, G_SMEM_BYTES>>>(phs, pwqkvT, pqkv, SEQ, QKVW, HID, 1);

    float* pk = pqkv + HID;
    float* pv = pqkv + HID + KVW;
    // Q: rounded + pre-scaled by 1/sqrt(64); K: rounded
    norm_rope_kernel<<<(SEQ * NH * 32) / 256, 256>>>(pqkv, qw, pos, NH, QKVW, 0.125f);
    norm_rope_kernel<<<(SEQ * NKV * 32) / 256, 256>>>(pk, kw, pos, NKV, QKVW, 1.0f);

    attn_mma<<<dim3(SEQ / 128, NH), 256, AT_SMEM_BYTES>>>(pqkv, pk, pv, pa, QKVW, QKVW);

    // O-projection, full fp32 output
    gemm_mma<<<dim3(HID / 128, SEQ / 128), 256, G_SMEM_BYTES>>>(pa, pwoT, out, SEQ, HID, HID, 0);
}

// round 10
// speedup vs baseline: 1.0061x; 1.0061x over previous
#include <cuda_runtime.h>
#include <math.h>
#include <stdint.h>

#define SEQ 2048
#define HID 2048
#define NH 32
#define NKV 8
#define HD 64
#define KVW (NKV*HD)       /* 512 */
#define QKVW (HID + 2*KVW) /* 3072 */

// ---------------- scratch ------------------------------------------------------
__device__ float g_qkv[SEQ * QKVW];
__device__ float g_att[SEQ * HID];
__device__ float g_hs32[SEQ * HID];
__device__ float g_wqkvT[QKVW * HID];
__device__ float g_woT[HID * HID];

// ================= helpers =================
__device__ __forceinline__ uint32_t smem_u32(const void* p) {
    uint32_t a;
    asm("{ .reg .u64 t; cvta.to.shared.u64 t, %1; cvt.u32.u64 %0, t; }" : "=r"(a) : "l"(p));
    return a;
}
__device__ __forceinline__ uint32_t f2tf32(float f) {
    uint32_t r;
    asm("cvt.rna.tf32.f32 %0, %1;" : "=r"(r) : "f"(f));
    return r;
}
__device__ __forceinline__ float f2tf32f(float f) {
    return __uint_as_float(f2tf32(f));
}
__device__ __forceinline__ float ex2(float x) {   // guaranteed MUFU.EX2
    float r;
    asm("ex2.approx.ftz.f32 %0, %1;" : "=f"(r) : "f"(x));
    return r;
}
#define CP_ASYNC16(dst, src) \
    asm volatile("cp.async.cg.shared.global [%0], [%1], 16;" :: "r"(dst), "l"(src))
#define CP_COMMIT() asm volatile("cp.async.commit_group;" ::: "memory")
#define CP_WAIT(n)  asm volatile("cp.async.wait_group %0;" :: "n"(n) : "memory")

__device__ __forceinline__ void mma_tf32_16x8x8(float& c0, float& c1, float& c2, float& c3,
                                                uint32_t a0, uint32_t a1, uint32_t a2, uint32_t a3,
                                                uint32_t b0, uint32_t b1) {
    asm volatile(
        "mma.sync.aligned.m16n8k8.row.col.f32.tf32.tf32.f32 "
        "{%0,%1,%2,%3}, {%4,%5,%6,%7}, {%8,%9}, {%0,%1,%2,%3};"
        : "+f"(c0), "+f"(c1), "+f"(c2), "+f"(c3)
        : "r"(a0), "r"(a1), "r"(a2), "r"(a3), "r"(b0), "r"(b1));
}

// ---------------- elementwise tf32-round copy ---------------------------------
__global__ __launch_bounds__(256)
void round_copy(const float* __restrict__ in, float* __restrict__ out)
{
    const int i = (blockIdx.x * 256 + threadIdx.x) * 4;
    float4 v = *(const float4*)(in + i);
    v.x = f2tf32f(v.x); v.y = f2tf32f(v.y);
    v.z = f2tf32f(v.z); v.w = f2tf32f(v.w);
    *(float4*)(out + i) = v;
}

// ---------------- weight transpose + tf32 round -------------------------------
__global__ __launch_bounds__(256)
void transpose32(const float* __restrict__ in, float* __restrict__ out, int K, int N)
{
    __shared__ float t[32][33];
    const int bx = blockIdx.x * 32;
    const int by = blockIdx.y * 32;
    const int tx = threadIdx.x, ty = threadIdx.y;
#pragma unroll
    for (int i = 0; i < 32; i += 8)
        t[ty + i][tx] = in[(size_t)(by + ty + i) * N + bx + tx];
    __syncthreads();
#pragma unroll
    for (int i = 0; i < 32; i += 8)
        out[(size_t)(bx + ty + i) * K + by + tx] = f2tf32f(t[tx][ty + i]);
}

// ---------------- tf32 mma.sync GEMM ------------------------------------------
#define GPAD 36
#define GBUF (128 * GPAD)
#define G_SMEM_BYTES (4 * GBUF * 4)

__global__ __launch_bounds__(256)
void gemm_mma(const float* __restrict__ A, const float* __restrict__ BT,
              float* __restrict__ C, int M, int N, int K, int roundOut)
{
    extern __shared__ float sm[];
    float* sA = sm;
    float* sB = sm + 2 * GBUF;

    const int tid  = threadIdx.x;
    const int wid  = tid >> 5;
    const int lane = tid & 31;
    const int g    = lane >> 2;
    const int tg   = lane & 3;
    const int wm   = (wid & 3) * 32;
    const int wn   = (wid >> 2) * 64;
    const int m0 = blockIdx.y * 128;
    const int n0 = blockIdx.x * 128;

    const int lrow  = tid >> 1;
    const int lcol  = (tid & 1) * 16;
    const float* gA = A  + (size_t)(m0 + lrow) * K + lcol;
    const float* gB = BT + (size_t)(n0 + lrow) * K + lcol;
    const uint32_t sbase = smem_u32(sm);
    const uint32_t sArow = sbase + (uint32_t)(lrow * GPAD + lcol) * 4u;
    const uint32_t sBrow = sArow + 2u * GBUF * 4u;

    float acc[2][8][4];
#pragma unroll
    for (int mt = 0; mt < 2; mt++)
#pragma unroll
        for (int nt = 0; nt < 8; nt++)
#pragma unroll
            for (int i = 0; i < 4; i++) acc[mt][nt][i] = 0.f;

    const int nch = K >> 5;
    {
#pragma unroll
        for (int j = 0; j < 4; j++) {
            CP_ASYNC16(sArow + j * 16u, gA + j * 4);
            CP_ASYNC16(sBrow + j * 16u, gB + j * 4);
        }
        CP_COMMIT();
    }

    for (int c = 0; c < nch; ++c) {
        const int buf = c & 1;
        if (c + 1 < nch) {
            const uint32_t off = (uint32_t)(((c + 1) & 1) * GBUF) * 4u;
            const float* pa = gA + (c + 1) * 32;
            const float* pb = gB + (c + 1) * 32;
#pragma unroll
            for (int j = 0; j < 4; j++) {
                CP_ASYNC16(sArow + off + j * 16u, pa + j * 4);
                CP_ASYNC16(sBrow + off + j * 16u, pb + j * 4);
            }
            CP_COMMIT();
            CP_WAIT(1);
        } else {
            CP_WAIT(0);
        }
        __syncthreads();

        const float* tA = sA + buf * GBUF;
        const float* tB = sB + buf * GBUF;

#pragma unroll
        for (int ks = 0; ks < 4; ++ks) {
            const int kk = ks * 8 + tg;
            uint32_t af[2][4];
#pragma unroll
            for (int mt = 0; mt < 2; mt++) {
                const int r = wm + mt * 16 + g;
                af[mt][0] = __float_as_uint(tA[r * GPAD + kk]);
                af[mt][1] = __float_as_uint(tA[(r + 8) * GPAD + kk]);
                af[mt][2] = __float_as_uint(tA[r * GPAD + kk + 4]);
                af[mt][3] = __float_as_uint(tA[(r + 8) * GPAD + kk + 4]);
            }
            uint32_t bf[8][2];
#pragma unroll
            for (int nt = 0; nt < 8; nt++) {
                const int r = wn + nt * 8 + g;
                bf[nt][0] = __float_as_uint(tB[r * GPAD + kk]);
                bf[nt][1] = __float_as_uint(tB[r * GPAD + kk + 4]);
            }
#pragma unroll
            for (int mt = 0; mt < 2; mt++)
#pragma unroll
                for (int nt = 0; nt < 8; nt++)
                    mma_tf32_16x8x8(acc[mt][nt][0], acc[mt][nt][1],
                                    acc[mt][nt][2], acc[mt][nt][3],
                                    af[mt][0], af[mt][1], af[mt][2], af[mt][3],
                                    bf[nt][0], bf[nt][1]);
        }
        __syncthreads();
    }

#pragma unroll
    for (int mt = 0; mt < 2; mt++) {
        const int r0 = m0 + wm + mt * 16 + g;
#pragma unroll
        for (int nt = 0; nt < 8; nt++) {
            const int col = n0 + wn + nt * 8 + 2 * tg;
            float2 v0 = make_float2(acc[mt][nt][0], acc[mt][nt][1]);
            float2 v1 = make_float2(acc[mt][nt][2], acc[mt][nt][3]);
            if (roundOut) {
                v0.x = f2tf32f(v0.x); v0.y = f2tf32f(v0.y);
                v1.x = f2tf32f(v1.x); v1.y = f2tf32f(v1.y);
            }
            *(float2*)(C + (size_t)r0 * N + col) = v0;
            *(float2*)(C + (size_t)(r0 + 8) * N + col) = v1;
        }
    }
}

// ---------------- fused per-head RMSNorm + RoPE (rounded, scaled store) -------
__global__ __launch_bounds__(256)
void norm_rope_kernel(float* __restrict__ x, const float* __restrict__ w,
                      const int* __restrict__ pos, int nheads, int rw, float scale)
{
    const int gw = (blockIdx.x * blockDim.x + threadIdx.x) >> 5;
    const int lane = threadIdx.x & 31;
    const int total = SEQ * nheads;
    if (gw >= total) return;
    const int s = gw / nheads;
    const int hh = gw - s * nheads;

    float* p = x + (size_t)s * rw + hh * HD;
    float x0 = p[lane];
    float x1 = p[lane + 32];

    float ss = x0 * x0 + x1 * x1;
#pragma unroll
    for (int o = 16; o; o >>= 1) ss += __shfl_xor_sync(0xffffffffu, ss, o);
    const float inv = rsqrtf(ss * (1.f / 64.f) + 1e-6f);
    x0 *= inv * w[lane];
    x1 *= inv * w[lane + 32];

    const float ang = (float)pos[s] * __expf(-(float)lane * (1.f / 32.f) * 9.2103403719761836f);
    float sn, c;
    sincosf(ang, &sn, &c);
    p[lane]      = f2tf32f((x0 * c - x1 * sn) * scale);
    p[lane + 32] = f2tf32f((x1 * c + x0 * sn) * scale);
}

// ---------------- causal flash attention --------------------------------------
// cp.async double-buffered K/V (natural [j][d], pre-rounded tf32 in gmem).
// P@V A-fragments built from S accumulators via quad shuffles (no smem staging).
#define APAD 68
#define KVTILE (64 * APAD)
#define AT_SMEM_FLOATS (4 * KVTILE)
#define AT_SMEM_BYTES  (AT_SMEM_FLOATS * 4)    /* 69632 B */
#define L2E 1.4426950408889634f

__global__ __launch_bounds__(256)
void attn_mma(const float* __restrict__ qb, const float* __restrict__ kb,
              const float* __restrict__ vb, float* __restrict__ ob,
              int ldq, int ldkv)
{
    extern __shared__ float sm[];

    const int tid = threadIdx.x;
    const int wid = tid >> 5;
    const int lane = tid & 31;
    const int g = lane >> 2;
    const int tg = lane & 3;
    const int qt = (int)gridDim.x - 1 - (int)blockIdx.x;  // LPT
    const int h = blockIdx.y;
    const int kvh = h >> 2;

    // loader mapping
    const int lr = tid >> 2;
    const int lc4 = (tid & 3) * 16;
    const uint32_t sbase = smem_u32(sm);
    const uint32_t sKrow0 = sbase + (uint32_t)(lr * APAD + lc4) * 4u;
    const float* kbase = kb + (size_t)kvh * HD + lc4;
    const float* vbase = vb + (size_t)kvh * HD + lc4;

    // ---- Q fragments (pre-rounded, pre-scaled in gmem) ----
    uint32_t aq[8][4];
    {
        const float* qp = qb + (size_t)(qt * 128 + wid * 16) * ldq + h * HD;
#pragma unroll
        for (int ks = 0; ks < 8; ks++) {
            const int c0 = ks * 8 + tg;
            aq[ks][0] = __float_as_uint(qp[(size_t)g * ldq + c0]);
            aq[ks][1] = __float_as_uint(qp[(size_t)(g + 8) * ldq + c0]);
            aq[ks][2] = __float_as_uint(qp[(size_t)g * ldq + c0 + 4]);
            aq[ks][3] = __float_as_uint(qp[(size_t)(g + 8) * ldq + c0 + 4]);
        }
    }

    float o[8][4];
#pragma unroll
    for (int nt = 0; nt < 8; nt++)
#pragma unroll
        for (int i = 0; i < 4; i++) o[nt][i] = 0.f;
    float m0 = -1e30f, m1 = -1e30f, l0 = 0.f, l1 = 0.f;

    const int r0g = qt * 128 + wid * 16 + g;
    const int r1g = r0g + 8;
    const int nkt = 2 * qt + 2;

    // ---- prefetch tile 0 ----
    {
        const float* kp = kbase + (size_t)lr * ldkv;
        const float* vp = vbase + (size_t)lr * ldkv;
#pragma unroll
        for (int j = 0; j < 4; j++) {
            CP_ASYNC16(sKrow0 + j * 16u, kp + j * 4);
            CP_ASYNC16(sKrow0 + (uint32_t)KVTILE * 4u + j * 16u, vp + j * 4);
        }
        CP_COMMIT();
    }

    for (int kt = 0; kt < nkt; ++kt) {
        if (kt + 1 < nkt) {
            const uint32_t boff = (uint32_t)(((kt + 1) & 1) * 2 * KVTILE) * 4u;
            const float* kp = kbase + (size_t)((kt + 1) * 64 + lr) * ldkv;
            const float* vp = vbase + (size_t)((kt + 1) * 64 + lr) * ldkv;
#pragma unroll
            for (int j = 0; j < 4; j++) {
                CP_ASYNC16(sKrow0 + boff + j * 16u, kp + j * 4);
                CP_ASYNC16(sKrow0 + boff + (uint32_t)KVTILE * 4u + j * 16u, vp + j * 4);
            }
            CP_COMMIT();
            CP_WAIT(1);
        } else {
            CP_WAIT(0);
        }
        __syncthreads();

        const float* Ks = sm + (kt & 1) * 2 * KVTILE;
        const float* Vs = Ks + KVTILE;

        const bool active = !(kt == 2 * qt + 1 && wid < 4);
        if (active) {
            // ---- S = Q @ K^T ----
            float s[8][4];
#pragma unroll
            for (int nt = 0; nt < 8; nt++)
#pragma unroll
                for (int i = 0; i < 4; i++) s[nt][i] = 0.f;

#pragma unroll
            for (int ks = 0; ks < 8; ks++) {
                const int kk = ks * 8 + tg;
#pragma unroll
                for (int nt = 0; nt < 8; nt++) {
                    const uint32_t b0 = __float_as_uint(Ks[(nt * 8 + g) * APAD + kk]);
                    const uint32_t b1 = __float_as_uint(Ks[(nt * 8 + g) * APAD + kk + 4]);
                    mma_tf32_16x8x8(s[nt][0], s[nt][1], s[nt][2], s[nt][3],
                                    aq[ks][0], aq[ks][1], aq[ks][2], aq[ks][3],
                                    b0, b1);
                }
            }

            // ---- causal mask ----
            if (kt >= 2 * qt) {
#pragma unroll
                for (int nt = 0; nt < 8; nt++) {
                    const int j0 = kt * 64 + nt * 8 + 2 * tg;
                    if (j0 > r0g)     s[nt][0] = -1e30f;
                    if (j0 + 1 > r0g) s[nt][1] = -1e30f;
                    if (j0 > r1g)     s[nt][2] = -1e30f;
                    if (j0 + 1 > r1g) s[nt][3] = -1e30f;
                }
            }

            // ---- online softmax (MUFU ex2) ----
            float mx0 = -1e30f, mx1 = -1e30f;
#pragma unroll
            for (int nt = 0; nt < 8; nt++) {
                mx0 = fmaxf(mx0, fmaxf(s[nt][0], s[nt][1]));
                mx1 = fmaxf(mx1, fmaxf(s[nt][2], s[nt][3]));
            }
            mx0 = fmaxf(mx0, __shfl_xor_sync(0xffffffffu, mx0, 1));
            mx0 = fmaxf(mx0, __shfl_xor_sync(0xffffffffu, mx0, 2));
            mx1 = fmaxf(mx1, __shfl_xor_sync(0xffffffffu, mx1, 1));
            mx1 = fmaxf(mx1, __shfl_xor_sync(0xffffffffu, mx1, 2));

            const float mn0 = fmaxf(m0, mx0);
            const float mn1 = fmaxf(m1, mx1);
            const float al0 = ex2((m0 - mn0) * L2E);
            const float al1 = ex2((m1 - mn1) * L2E);
            float sum0 = 0.f, sum1 = 0.f;
#pragma unroll
            for (int nt = 0; nt < 8; nt++) {
                s[nt][0] = ex2((s[nt][0] - mn0) * L2E);
                s[nt][1] = ex2((s[nt][1] - mn0) * L2E);
                s[nt][2] = ex2((s[nt][2] - mn1) * L2E);
                s[nt][3] = ex2((s[nt][3] - mn1) * L2E);
                sum0 += s[nt][0] + s[nt][1];
                sum1 += s[nt][2] + s[nt][3];
            }
            sum0 += __shfl_xor_sync(0xffffffffu, sum0, 1);
            sum0 += __shfl_xor_sync(0xffffffffu, sum0, 2);
            sum1 += __shfl_xor_sync(0xffffffffu, sum1, 1);
            sum1 += __shfl_xor_sync(0xffffffffu, sum1, 2);
            m0 = mn0; m1 = mn1;
            l0 = l0 * al0 + sum0;
            l1 = l1 * al1 + sum1;
#pragma unroll
            for (int nt = 0; nt < 8; nt++) {
                o[nt][0] *= al0; o[nt][1] *= al0;
                o[nt][2] *= al1; o[nt][3] *= al1;
            }

            // ---- O += P @ V: A-fragments via quad shuffles from s[][] ----
            const int qbase = lane & ~3;
            const int s1 = qbase + (tg >> 1);
            const int s2 = s1 + 2;
            const bool odd = (tg & 1);
#pragma unroll
            for (int ks = 0; ks < 8; ks++) {
                const float v0 = __shfl_sync(0xffffffffu, s[ks][0], s1);
                const float v1 = __shfl_sync(0xffffffffu, s[ks][1], s1);
                const float v2 = __shfl_sync(0xffffffffu, s[ks][2], s1);
                const float v3 = __shfl_sync(0xffffffffu, s[ks][3], s1);
                const float w0 = __shfl_sync(0xffffffffu, s[ks][0], s2);
                const float w1 = __shfl_sync(0xffffffffu, s[ks][1], s2);
                const float w2 = __shfl_sync(0xffffffffu, s[ks][2], s2);
                const float w3 = __shfl_sync(0xffffffffu, s[ks][3], s2);
                const uint32_t a0 = f2tf32(odd ? v1 : v0);
                const uint32_t a1 = f2tf32(odd ? v3 : v2);
                const uint32_t a2 = f2tf32(odd ? w1 : w0);
                const uint32_t a3 = f2tf32(odd ? w3 : w2);
                const int kk = ks * 8 + tg;
#pragma unroll
                for (int nt = 0; nt < 8; nt++) {
                    const uint32_t b0 = __float_as_uint(Vs[kk * APAD + nt * 8 + g]);
                    const uint32_t b1 = __float_as_uint(Vs[(kk + 4) * APAD + nt * 8 + g]);
                    mma_tf32_16x8x8(o[nt][0], o[nt][1], o[nt][2], o[nt][3],
                                    a0, a1, a2, a3, b0, b1);
                }
            }
        }
        __syncthreads();
    }

    // ---- epilogue: tf32-round (feeds O-proj A operand) ----
    const float il0 = 1.f / l0;
    const float il1 = 1.f / l1;
#pragma unroll
    for (int nt = 0; nt < 8; nt++) {
        const int col = h * HD + nt * 8 + 2 * tg;
        *(float2*)(ob + (size_t)r0g * HID + col) =
            make_float2(f2tf32f(o[nt][0] * il0), f2tf32f(o[nt][1] * il0));
        *(float2*)(ob + (size_t)r1g * HID + col) =
            make_float2(f2tf32f(o[nt][2] * il1), f2tf32f(o[nt][3] * il1));
    }
}

// ---------------- launch ------------------------------------------------------
extern "C" void kernel_launch(void* const* d_in, const int* in_sizes, int n_in,
                              void* d_out, int out_size)
{
    const float* hs  = (const float*)d_in[0];
    const int*   pos = (const int*)  d_in[1];
    const float* wq  = (const float*)d_in[2];
    const float* wk  = (const float*)d_in[3];
    const float* wv  = (const float*)d_in[4];
    const float* wo  = (const float*)d_in[5];
    const float* qw  = (const float*)d_in[6];
    const float* kw  = (const float*)d_in[7];
    float* out = (float*)d_out;

    float *pqkv, *pa, *phs, *pwqkvT, *pwoT;
    cudaGetSymbolAddress((void**)&pqkv, g_qkv);
    cudaGetSymbolAddress((void**)&pa, g_att);
    cudaGetSymbolAddress((void**)&phs, g_hs32);
    cudaGetSymbolAddress((void**)&pwqkvT, g_wqkvT);
    cudaGetSymbolAddress((void**)&pwoT, g_woT);

    cudaFuncSetAttribute(gemm_mma, cudaFuncAttributeMaxDynamicSharedMemorySize,
                         G_SMEM_BYTES);
    cudaFuncSetAttribute(attn_mma, cudaFuncAttributeMaxDynamicSharedMemorySize,
                         AT_SMEM_BYTES);

    dim3 tb(32, 8);
    round_copy<<<(SEQ * HID) / 1024, 256>>>(hs, phs);
    transpose32<<<dim3(HID / 32, HID / 32), tb>>>(wq, pwqkvT, HID, HID);
    transpose32<<<dim3(KVW / 32, HID / 32), tb>>>(wk, pwqkvT + (size_t)HID * HID, HID, KVW);
    transpose32<<<dim3(KVW / 32, HID / 32), tb>>>(wv, pwqkvT + (size_t)(HID + KVW) * HID, HID, KVW);
    transpose32<<<dim3(HID / 32, HID / 32), tb>>>(wo, pwoT, HID, HID);

    gemm_mma<<<dim3(QKVW / 128, SEQ / 128), 256, G_SMEM_BYTES>>>(phs, pwqkvT, pqkv, SEQ, QKVW, HID, 1);

    float* pk = pqkv + HID;
    float* pv = pqkv + HID + KVW;
    norm_rope_kernel<<<(SEQ * NH * 32) / 256, 256>>>(pqkv, qw, pos, NH, QKVW, 0.125f);
    norm_rope_kernel<<<(SEQ * NKV * 32) / 256, 256>>>(pk, kw, pos, NKV, QKVW, 1.0f);

    attn_mma<<<dim3(SEQ / 128, NH), 256, AT_SMEM_BYTES>>>(pqkv, pk, pv, pa, QKVW, QKVW);

    gemm_mma<<<dim3(HID / 128, SEQ / 128), 256, G_SMEM_BYTES>>>(pa, pwoT, out, SEQ, HID, HID, 0);
}

// round 11
// speedup vs baseline: 1.1087x; 1.1020x over previous
#include <cuda_runtime.h>
#include <math.h>
#include <stdint.h>

#define SEQ 2048
#define HID 2048
#define NH 32
#define NKV 8
#define HD 64
#define KVW (NKV*HD)       /* 512 */
#define QKVW (HID + 2*KVW) /* 3072 */

// ---------------- scratch ------------------------------------------------------
__device__ float g_qkv[SEQ * QKVW];
__device__ float g_att[SEQ * HID];
__device__ float g_hs32[SEQ * HID];
__device__ float g_wqkvT[QKVW * HID];
__device__ float g_woT[HID * HID];

// ================= helpers =================
__device__ __forceinline__ uint32_t smem_u32(const void* p) {
    uint32_t a;
    asm("{ .reg .u64 t; cvta.to.shared.u64 t, %1; cvt.u32.u64 %0, t; }" : "=r"(a) : "l"(p));
    return a;
}
__device__ __forceinline__ uint32_t f2tf32(float f) {
    uint32_t r;
    asm("cvt.rna.tf32.f32 %0, %1;" : "=r"(r) : "f"(f));
    return r;
}
__device__ __forceinline__ float f2tf32f(float f) {
    return __uint_as_float(f2tf32(f));
}
__device__ __forceinline__ float ex2(float x) {
    float r;
    asm("ex2.approx.ftz.f32 %0, %1;" : "=f"(r) : "f"(x));
    return r;
}
#define CP_ASYNC16(dst, src) \
    asm volatile("cp.async.cg.shared.global [%0], [%1], 16;" :: "r"(dst), "l"(src))
#define CP_COMMIT() asm volatile("cp.async.commit_group;" ::: "memory")
#define CP_WAIT(n)  asm volatile("cp.async.wait_group %0;" :: "n"(n) : "memory")

__device__ __forceinline__ void mma_tf32_16x8x8(float& c0, float& c1, float& c2, float& c3,
                                                uint32_t a0, uint32_t a1, uint32_t a2, uint32_t a3,
                                                uint32_t b0, uint32_t b1) {
    asm volatile(
        "mma.sync.aligned.m16n8k8.row.col.f32.tf32.tf32.f32 "
        "{%0,%1,%2,%3}, {%4,%5,%6,%7}, {%8,%9}, {%0,%1,%2,%3};"
        : "+f"(c0), "+f"(c1), "+f"(c2), "+f"(c3)
        : "r"(a0), "r"(a1), "r"(a2), "r"(a3), "r"(b0), "r"(b1));
}

// ---------------- fused prologue: round_copy + 4 weight transposes ------------
// blocks [0,4096): hs round-copy; [4096,8192): wq^T; [8192,9216): wk^T;
// [9216,10240): wv^T; [10240,14336): wo^T
__global__ __launch_bounds__(256)
void prep_kernel(const float* __restrict__ hs, const float* __restrict__ wq,
                 const float* __restrict__ wk, const float* __restrict__ wv,
                 const float* __restrict__ wo,
                 float* __restrict__ hs32, float* __restrict__ wqkvT,
                 float* __restrict__ woT)
{
    const int bx = blockIdx.x;
    const int tid = threadIdx.x;

    if (bx < 4096) {                       // tf32-round copy of hidden states
        const int i = (bx * 256 + tid) * 4;
        float4 v = *(const float4*)(hs + i);
        v.x = f2tf32f(v.x); v.y = f2tf32f(v.y);
        v.z = f2tf32f(v.z); v.w = f2tf32f(v.w);
        *(float4*)(hs32 + i) = v;
        return;
    }

    __shared__ float t[32][33];
    const int tx = tid & 31;
    const int ty = tid >> 5;
    const float* in;
    float* out;
    int N, lb;
    if (bx < 8192)       { in = wq; out = wqkvT;                          N = HID; lb = bx - 4096; }
    else if (bx < 9216)  { in = wk; out = wqkvT + (size_t)HID * HID;      N = KVW; lb = bx - 8192; }
    else if (bx < 10240) { in = wv; out = wqkvT + (size_t)(HID+KVW)*HID;  N = KVW; lb = bx - 9216; }
    else                 { in = wo; out = woT;                            N = HID; lb = bx - 10240; }
    const int gw = N / 32;
    const int bxx = (lb % gw) * 32;        // over N
    const int byy = (lb / gw) * 32;        // over K(=HID)
#pragma unroll
    for (int i = 0; i < 32; i += 8)
        t[ty + i][tx] = in[(size_t)(byy + ty + i) * N + bxx + tx];
    __syncthreads();
#pragma unroll
    for (int i = 0; i < 32; i += 8)
        out[(size_t)(bxx + ty + i) * HID + byy + tx] = f2tf32f(t[tx][ty + i]);
}

// ---------------- tf32 mma.sync GEMM ------------------------------------------
#define GPAD 36
#define GBUF (128 * GPAD)
#define G_SMEM_BYTES (4 * GBUF * 4)

__global__ __launch_bounds__(256)
void gemm_mma(const float* __restrict__ A, const float* __restrict__ BT,
              float* __restrict__ C, int M, int N, int K, int roundOut)
{
    extern __shared__ float sm[];
    float* sA = sm;
    float* sB = sm + 2 * GBUF;

    const int tid  = threadIdx.x;
    const int wid  = tid >> 5;
    const int lane = tid & 31;
    const int g    = lane >> 2;
    const int tg   = lane & 3;
    const int wm   = (wid & 3) * 32;
    const int wn   = (wid >> 2) * 64;
    const int m0 = blockIdx.y * 128;
    const int n0 = blockIdx.x * 128;

    const int lrow  = tid >> 1;
    const int lcol  = (tid & 1) * 16;
    const float* gA = A  + (size_t)(m0 + lrow) * K + lcol;
    const float* gB = BT + (size_t)(n0 + lrow) * K + lcol;
    const uint32_t sbase = smem_u32(sm);
    const uint32_t sArow = sbase + (uint32_t)(lrow * GPAD + lcol) * 4u;
    const uint32_t sBrow = sArow + 2u * GBUF * 4u;

    float acc[2][8][4];
#pragma unroll
    for (int mt = 0; mt < 2; mt++)
#pragma unroll
        for (int nt = 0; nt < 8; nt++)
#pragma unroll
            for (int i = 0; i < 4; i++) acc[mt][nt][i] = 0.f;

    const int nch = K >> 5;
    {
#pragma unroll
        for (int j = 0; j < 4; j++) {
            CP_ASYNC16(sArow + j * 16u, gA + j * 4);
            CP_ASYNC16(sBrow + j * 16u, gB + j * 4);
        }
        CP_COMMIT();
    }

    for (int c = 0; c < nch; ++c) {
        const int buf = c & 1;
        if (c + 1 < nch) {
            const uint32_t off = (uint32_t)(((c + 1) & 1) * GBUF) * 4u;
            const float* pa = gA + (c + 1) * 32;
            const float* pb = gB + (c + 1) * 32;
#pragma unroll
            for (int j = 0; j < 4; j++) {
                CP_ASYNC16(sArow + off + j * 16u, pa + j * 4);
                CP_ASYNC16(sBrow + off + j * 16u, pb + j * 4);
            }
            CP_COMMIT();
            CP_WAIT(1);
        } else {
            CP_WAIT(0);
        }
        __syncthreads();

        const float* tA = sA + buf * GBUF;
        const float* tB = sB + buf * GBUF;

#pragma unroll
        for (int ks = 0; ks < 4; ++ks) {
            const int kk = ks * 8 + tg;
            uint32_t af[2][4];
#pragma unroll
            for (int mt = 0; mt < 2; mt++) {
                const int r = wm + mt * 16 + g;
                af[mt][0] = __float_as_uint(tA[r * GPAD + kk]);
                af[mt][1] = __float_as_uint(tA[(r + 8) * GPAD + kk]);
                af[mt][2] = __float_as_uint(tA[r * GPAD + kk + 4]);
                af[mt][3] = __float_as_uint(tA[(r + 8) * GPAD + kk + 4]);
            }
            uint32_t bf[8][2];
#pragma unroll
            for (int nt = 0; nt < 8; nt++) {
                const int r = wn + nt * 8 + g;
                bf[nt][0] = __float_as_uint(tB[r * GPAD + kk]);
                bf[nt][1] = __float_as_uint(tB[r * GPAD + kk + 4]);
            }
#pragma unroll
            for (int mt = 0; mt < 2; mt++)
#pragma unroll
                for (int nt = 0; nt < 8; nt++)
                    mma_tf32_16x8x8(acc[mt][nt][0], acc[mt][nt][1],
                                    acc[mt][nt][2], acc[mt][nt][3],
                                    af[mt][0], af[mt][1], af[mt][2], af[mt][3],
                                    bf[nt][0], bf[nt][1]);
        }
        __syncthreads();
    }

#pragma unroll
    for (int mt = 0; mt < 2; mt++) {
        const int r0 = m0 + wm + mt * 16 + g;
#pragma unroll
        for (int nt = 0; nt < 8; nt++) {
            const int col = n0 + wn + nt * 8 + 2 * tg;
            float2 v0 = make_float2(acc[mt][nt][0], acc[mt][nt][1]);
            float2 v1 = make_float2(acc[mt][nt][2], acc[mt][nt][3]);
            if (roundOut) {
                v0.x = f2tf32f(v0.x); v0.y = f2tf32f(v0.y);
                v1.x = f2tf32f(v1.x); v1.y = f2tf32f(v1.y);
            }
            *(float2*)(C + (size_t)r0 * N + col) = v0;
            *(float2*)(C + (size_t)(r0 + 8) * N + col) = v1;
        }
    }
}

// ---------------- fused RMSNorm + RoPE (q + k in one launch) ------------------
// blocks [0,8192): q-heads (scale 0.125); [8192,10240): k-heads (scale 1)
__global__ __launch_bounds__(256)
void norm_rope_all(float* __restrict__ qkv, const float* __restrict__ qw,
                   const float* __restrict__ kw, const int* __restrict__ pos)
{
    const int bx = blockIdx.x;
    float* x; const float* w; int nheads; float scale; int lb;
    if (bx < 8192) { x = qkv;       w = qw; nheads = NH;  scale = 0.125f; lb = bx; }
    else           { x = qkv + HID; w = kw; nheads = NKV; scale = 1.0f;   lb = bx - 8192; }

    const int gw = (lb * 256 + (int)threadIdx.x) >> 5;
    const int lane = threadIdx.x & 31;
    const int s = gw / nheads;
    const int hh = gw - s * nheads;

    float* p = x + (size_t)s * QKVW + hh * HD;
    float x0 = p[lane];
    float x1 = p[lane + 32];

    float ss = x0 * x0 + x1 * x1;
#pragma unroll
    for (int o = 16; o; o >>= 1) ss += __shfl_xor_sync(0xffffffffu, ss, o);
    const float inv = rsqrtf(ss * (1.f / 64.f) + 1e-6f);
    x0 *= inv * w[lane];
    x1 *= inv * w[lane + 32];

    const float ang = (float)pos[s] * __expf(-(float)lane * (1.f / 32.f) * 9.2103403719761836f);
    float sn, c;
    sincosf(ang, &sn, &c);
    p[lane]      = f2tf32f((x0 * c - x1 * sn) * scale);
    p[lane + 32] = f2tf32f((x1 * c + x0 * sn) * scale);
}

// ---------------- causal flash attention --------------------------------------
// 1D grid, global LPT: qt = 15 - bx/32 (heaviest blocks launch first).
// cp.async double-buffered K/V natural layout; exact diagonal block skipping.
#define APAD 68
#define KVTILE (64 * APAD)
#define AT_SMEM_FLOATS (4 * KVTILE)
#define AT_SMEM_BYTES  (AT_SMEM_FLOATS * 4)    /* 69632 B */
#define L2E 1.4426950408889634f

__global__ __launch_bounds__(256)
void attn_mma(const float* __restrict__ qb, const float* __restrict__ kb,
              const float* __restrict__ vb, float* __restrict__ ob,
              int ldq, int ldkv)
{
    extern __shared__ float sm[];

    const int tid = threadIdx.x;
    const int wid = tid >> 5;
    const int lane = tid & 31;
    const int g = lane >> 2;
    const int tg = lane & 3;
    const int nqt = SEQ / 128;                       // 16
    const int qt = nqt - 1 - ((int)blockIdx.x >> 5); // global LPT
    const int h = (int)blockIdx.x & 31;
    const int kvh = h >> 2;
    const int dlim = 2 * wid + 2;                    // diagonal-tile block limit

    const int lr = tid >> 2;
    const int lc4 = (tid & 3) * 16;
    const uint32_t sbase = smem_u32(sm);
    const uint32_t sKrow0 = sbase + (uint32_t)(lr * APAD + lc4) * 4u;
    const float* kbase = kb + (size_t)kvh * HD + lc4;
    const float* vbase = vb + (size_t)kvh * HD + lc4;

    // ---- Q fragments (pre-rounded, pre-scaled in gmem) ----
    uint32_t aq[8][4];
    {
        const float* qp = qb + (size_t)(qt * 128 + wid * 16) * ldq + h * HD;
#pragma unroll
        for (int ks = 0; ks < 8; ks++) {
            const int c0 = ks * 8 + tg;
            aq[ks][0] = __float_as_uint(qp[(size_t)g * ldq + c0]);
            aq[ks][1] = __float_as_uint(qp[(size_t)(g + 8) * ldq + c0]);
            aq[ks][2] = __float_as_uint(qp[(size_t)g * ldq + c0 + 4]);
            aq[ks][3] = __float_as_uint(qp[(size_t)(g + 8) * ldq + c0 + 4]);
        }
    }

    float o[8][4];
#pragma unroll
    for (int nt = 0; nt < 8; nt++)
#pragma unroll
        for (int i = 0; i < 4; i++) o[nt][i] = 0.f;
    float m0 = -1e30f, m1 = -1e30f, l0 = 0.f, l1 = 0.f;

    const int r0g = qt * 128 + wid * 16 + g;
    const int r1g = r0g + 8;
    const int nkt = 2 * qt + 2;

    // ---- prefetch tile 0 ----
    {
        const float* kp = kbase + (size_t)lr * ldkv;
        const float* vp = vbase + (size_t)lr * ldkv;
#pragma unroll
        for (int j = 0; j < 4; j++) {
            CP_ASYNC16(sKrow0 + j * 16u, kp + j * 4);
            CP_ASYNC16(sKrow0 + (uint32_t)KVTILE * 4u + j * 16u, vp + j * 4);
        }
        CP_COMMIT();
    }

    for (int kt = 0; kt < nkt; ++kt) {
        if (kt + 1 < nkt) {
            const uint32_t boff = (uint32_t)(((kt + 1) & 1) * 2 * KVTILE) * 4u;
            const float* kp = kbase + (size_t)((kt + 1) * 64 + lr) * ldkv;
            const float* vp = vbase + (size_t)((kt + 1) * 64 + lr) * ldkv;
#pragma unroll
            for (int j = 0; j < 4; j++) {
                CP_ASYNC16(sKrow0 + boff + j * 16u, kp + j * 4);
                CP_ASYNC16(sKrow0 + boff + (uint32_t)KVTILE * 4u + j * 16u, vp + j * 4);
            }
            CP_COMMIT();
            CP_WAIT(1);
        } else {
            CP_WAIT(0);
        }
        __syncthreads();

        const float* Ks = sm + (kt & 1) * 2 * KVTILE;
        const float* Vs = Ks + KVTILE;

        const bool diag = (kt == 2 * qt);
        const bool active = !(kt == 2 * qt + 1 && wid < 4);
        if (active) {
            // ---- S = Q @ K^T (skip fully-masked nt blocks on diagonal) ----
            float s[8][4];
#pragma unroll
            for (int nt = 0; nt < 8; nt++)
#pragma unroll
                for (int i = 0; i < 4; i++) s[nt][i] = 0.f;

#pragma unroll
            for (int ks = 0; ks < 8; ks++) {
                const int kk = ks * 8 + tg;
#pragma unroll
                for (int nt = 0; nt < 8; nt++) {
                    if (diag && nt >= dlim) continue;
                    const uint32_t b0 = __float_as_uint(Ks[(nt * 8 + g) * APAD + kk]);
                    const uint32_t b1 = __float_as_uint(Ks[(nt * 8 + g) * APAD + kk + 4]);
                    mma_tf32_16x8x8(s[nt][0], s[nt][1], s[nt][2], s[nt][3],
                                    aq[ks][0], aq[ks][1], aq[ks][2], aq[ks][3],
                                    b0, b1);
                }
            }

            // ---- causal mask ----
            if (kt >= 2 * qt) {
#pragma unroll
                for (int nt = 0; nt < 8; nt++) {
                    const int j0 = kt * 64 + nt * 8 + 2 * tg;
                    if (j0 > r0g)     s[nt][0] = -1e30f;
                    if (j0 + 1 > r0g) s[nt][1] = -1e30f;
                    if (j0 > r1g)     s[nt][2] = -1e30f;
                    if (j0 + 1 > r1g) s[nt][3] = -1e30f;
                }
            }

            // ---- online softmax (MUFU ex2) ----
            float mx0 = -1e30f, mx1 = -1e30f;
#pragma unroll
            for (int nt = 0; nt < 8; nt++) {
                mx0 = fmaxf(mx0, fmaxf(s[nt][0], s[nt][1]));
                mx1 = fmaxf(mx1, fmaxf(s[nt][2], s[nt][3]));
            }
            mx0 = fmaxf(mx0, __shfl_xor_sync(0xffffffffu, mx0, 1));
            mx0 = fmaxf(mx0, __shfl_xor_sync(0xffffffffu, mx0, 2));
            mx1 = fmaxf(mx1, __shfl_xor_sync(0xffffffffu, mx1, 1));
            mx1 = fmaxf(mx1, __shfl_xor_sync(0xffffffffu, mx1, 2));

            const float mn0 = fmaxf(m0, mx0);
            const float mn1 = fmaxf(m1, mx1);
            const float al0 = ex2((m0 - mn0) * L2E);
            const float al1 = ex2((m1 - mn1) * L2E);
            float sum0 = 0.f, sum1 = 0.f;
#pragma unroll
            for (int nt = 0; nt < 8; nt++) {
                s[nt][0] = ex2((s[nt][0] - mn0) * L2E);
                s[nt][1] = ex2((s[nt][1] - mn0) * L2E);
                s[nt][2] = ex2((s[nt][2] - mn1) * L2E);
                s[nt][3] = ex2((s[nt][3] - mn1) * L2E);
                sum0 += s[nt][0] + s[nt][1];
                sum1 += s[nt][2] + s[nt][3];
            }
            sum0 += __shfl_xor_sync(0xffffffffu, sum0, 1);
            sum0 += __shfl_xor_sync(0xffffffffu, sum0, 2);
            sum1 += __shfl_xor_sync(0xffffffffu, sum1, 1);
            sum1 += __shfl_xor_sync(0xffffffffu, sum1, 2);
            m0 = mn0; m1 = mn1;
            l0 = l0 * al0 + sum0;
            l1 = l1 * al1 + sum1;
#pragma unroll
            for (int nt = 0; nt < 8; nt++) {
                o[nt][0] *= al0; o[nt][1] *= al0;
                o[nt][2] *= al1; o[nt][3] *= al1;
            }

            // ---- O += P @ V: A-frags via quad shuffles; skip zero ks on diag --
            const int qbase = lane & ~3;
            const int s1 = qbase + (tg >> 1);
            const int s2 = s1 + 2;
            const bool odd = (tg & 1);
#pragma unroll
            for (int ks = 0; ks < 8; ks++) {
                if (diag && ks >= dlim) continue;   // P exactly 0 there
                const float v0 = __shfl_sync(0xffffffffu, s[ks][0], s1);
                const float v1 = __shfl_sync(0xffffffffu, s[ks][1], s1);
                const float v2 = __shfl_sync(0xffffffffu, s[ks][2], s1);
                const float v3 = __shfl_sync(0xffffffffu, s[ks][3], s1);
                const float w0 = __shfl_sync(0xffffffffu, s[ks][0], s2);
                const float w1 = __shfl_sync(0xffffffffu, s[ks][1], s2);
                const float w2 = __shfl_sync(0xffffffffu, s[ks][2], s2);
                const float w3 = __shfl_sync(0xffffffffu, s[ks][3], s2);
                const uint32_t a0 = f2tf32(odd ? v1 : v0);
                const uint32_t a1 = f2tf32(odd ? v3 : v2);
                const uint32_t a2 = f2tf32(odd ? w1 : w0);
                const uint32_t a3 = f2tf32(odd ? w3 : w2);
                const int kk = ks * 8 + tg;
#pragma unroll
                for (int nt = 0; nt < 8; nt++) {
                    const uint32_t b0 = __float_as_uint(Vs[kk * APAD + nt * 8 + g]);
                    const uint32_t b1 = __float_as_uint(Vs[(kk + 4) * APAD + nt * 8 + g]);
                    mma_tf32_16x8x8(o[nt][0], o[nt][1], o[nt][2], o[nt][3],
                                    a0, a1, a2, a3, b0, b1);
                }
            }
        }
        __syncthreads();
    }

    // ---- epilogue: tf32-round (feeds O-proj A operand) ----
    const float il0 = 1.f / l0;
    const float il1 = 1.f / l1;
#pragma unroll
    for (int nt = 0; nt < 8; nt++) {
        const int col = h * HD + nt * 8 + 2 * tg;
        *(float2*)(ob + (size_t)r0g * HID + col) =
            make_float2(f2tf32f(o[nt][0] * il0), f2tf32f(o[nt][1] * il0));
        *(float2*)(ob + (size_t)r1g * HID + col) =
            make_float2(f2tf32f(o[nt][2] * il1), f2tf32f(o[nt][3] * il1));
    }
}

// ---------------- launch ------------------------------------------------------
extern "C" void kernel_launch(void* const* d_in, const int* in_sizes, int n_in,
                              void* d_out, int out_size)
{
    const float* hs  = (const float*)d_in[0];
    const int*   pos = (const int*)  d_in[1];
    const float* wq  = (const float*)d_in[2];
    const float* wk  = (const float*)d_in[3];
    const float* wv  = (const float*)d_in[4];
    const float* wo  = (const float*)d_in[5];
    const float* qw  = (const float*)d_in[6];
    const float* kw  = (const float*)d_in[7];
    float* out = (float*)d_out;

    float *pqkv, *pa, *phs, *pwqkvT, *pwoT;
    cudaGetSymbolAddress((void**)&pqkv, g_qkv);
    cudaGetSymbolAddress((void**)&pa, g_att);
    cudaGetSymbolAddress((void**)&phs, g_hs32);
    cudaGetSymbolAddress((void**)&pwqkvT, g_wqkvT);
    cudaGetSymbolAddress((void**)&pwoT, g_woT);

    cudaFuncSetAttribute(gemm_mma, cudaFuncAttributeMaxDynamicSharedMemorySize,
                         G_SMEM_BYTES);
    cudaFuncSetAttribute(attn_mma, cudaFuncAttributeMaxDynamicSharedMemorySize,
                         AT_SMEM_BYTES);

    // launch 0: fused prologue (round_copy + all 4 transposes)
    prep_kernel<<<14336, 256>>>(hs, wq, wk, wv, wo, phs, pwqkvT, pwoT);

    // launch 1: fused QKV projection (tf32-rounded output)
    gemm_mma<<<dim3(QKVW / 128, SEQ / 128), 256, G_SMEM_BYTES>>>(phs, pwqkvT, pqkv, SEQ, QKVW, HID, 1);

    // launch 2: fused q+k RMSNorm/RoPE
    norm_rope_all<<<10240, 256>>>(pqkv, qw, kw, pos);

    // launch 3: attention (this is the ncu-captured launch)
    float* pk = pqkv + HID;
    float* pv = pqkv + HID + KVW;
    attn_mma<<<512, 256, AT_SMEM_BYTES>>>(pqkv, pk, pv, pa, QKVW, QKVW);

    // launch 4: output projection
    gemm_mma<<<dim3(HID / 128, SEQ / 128), 256, G_SMEM_BYTES>>>(pa, pwoT, out, SEQ, HID, HID, 0);
}

// round 12
// speedup vs baseline: 1.1290x; 1.0184x over previous
#include <cuda_runtime.h>
#include <math.h>
#include <stdint.h>

#define SEQ 2048
#define HID 2048
#define NH 32
#define NKV 8
#define HD 64
#define KVW (NKV*HD)       /* 512 */
#define QKVW (HID + 2*KVW) /* 3072 */

// ---------------- scratch ------------------------------------------------------
__device__ float g_qkv[SEQ * QKVW];
__device__ float g_att[SEQ * HID];
__device__ float g_hs32[SEQ * HID];
__device__ float g_wqkvT[QKVW * HID];
__device__ float g_woT[HID * HID];

// ================= helpers =================
__device__ __forceinline__ uint32_t smem_u32(const void* p) {
    uint32_t a;
    asm("{ .reg .u64 t; cvta.to.shared.u64 t, %1; cvt.u32.u64 %0, t; }" : "=r"(a) : "l"(p));
    return a;
}
__device__ __forceinline__ uint32_t f2tf32(float f) {
    uint32_t r;
    asm("cvt.rna.tf32.f32 %0, %1;" : "=r"(r) : "f"(f));
    return r;
}
__device__ __forceinline__ float f2tf32f(float f) {
    return __uint_as_float(f2tf32(f));
}
__device__ __forceinline__ float ex2(float x) {
    float r;
    asm("ex2.approx.ftz.f32 %0, %1;" : "=f"(r) : "f"(x));
    return r;
}
#define CP_ASYNC16(dst, src) \
    asm volatile("cp.async.cg.shared.global [%0], [%1], 16;" :: "r"(dst), "l"(src))
#define CP_COMMIT() asm volatile("cp.async.commit_group;" ::: "memory")
#define CP_WAIT(n)  asm volatile("cp.async.wait_group %0;" :: "n"(n) : "memory")

__device__ __forceinline__ void mma_tf32_16x8x8(float& c0, float& c1, float& c2, float& c3,
                                                uint32_t a0, uint32_t a1, uint32_t a2, uint32_t a3,
                                                uint32_t b0, uint32_t b1) {
    asm volatile(
        "mma.sync.aligned.m16n8k8.row.col.f32.tf32.tf32.f32 "
        "{%0,%1,%2,%3}, {%4,%5,%6,%7}, {%8,%9}, {%0,%1,%2,%3};"
        : "+f"(c0), "+f"(c1), "+f"(c2), "+f"(c3)
        : "r"(a0), "r"(a1), "r"(a2), "r"(a3), "r"(b0), "r"(b1));
}

// ---------------- fused prologue: round_copy + 4 weight transposes ------------
__global__ __launch_bounds__(256)
void prep_kernel(const float* __restrict__ hs, const float* __restrict__ wq,
                 const float* __restrict__ wk, const float* __restrict__ wv,
                 const float* __restrict__ wo,
                 float* __restrict__ hs32, float* __restrict__ wqkvT,
                 float* __restrict__ woT)
{
    const int bx = blockIdx.x;
    const int tid = threadIdx.x;

    if (bx < 4096) {
        const int i = (bx * 256 + tid) * 4;
        float4 v = *(const float4*)(hs + i);
        v.x = f2tf32f(v.x); v.y = f2tf32f(v.y);
        v.z = f2tf32f(v.z); v.w = f2tf32f(v.w);
        *(float4*)(hs32 + i) = v;
        return;
    }

    __shared__ float t[32][33];
    const int tx = tid & 31;
    const int ty = tid >> 5;
    const float* in;
    float* out;
    int N, lb;
    if (bx < 8192)       { in = wq; out = wqkvT;                          N = HID; lb = bx - 4096; }
    else if (bx < 9216)  { in = wk; out = wqkvT + (size_t)HID * HID;      N = KVW; lb = bx - 8192; }
    else if (bx < 10240) { in = wv; out = wqkvT + (size_t)(HID+KVW)*HID;  N = KVW; lb = bx - 9216; }
    else                 { in = wo; out = woT;                            N = HID; lb = bx - 10240; }
    const int gw = N / 32;
    const int bxx = (lb % gw) * 32;
    const int byy = (lb / gw) * 32;
#pragma unroll
    for (int i = 0; i < 32; i += 8)
        t[ty + i][tx] = in[(size_t)(byy + ty + i) * N + bxx + tx];
    __syncthreads();
#pragma unroll
    for (int i = 0; i < 32; i += 8)
        out[(size_t)(bxx + ty + i) * HID + byy + tx] = f2tf32f(t[tx][ty + i]);
}

// ---------------- tf32 mma.sync GEMM ------------------------------------------
#define GPAD 36
#define GBUF (128 * GPAD)
#define G_SMEM_BYTES (4 * GBUF * 4)

__global__ __launch_bounds__(256)
void gemm_mma(const float* __restrict__ A, const float* __restrict__ BT,
              float* __restrict__ C, int M, int N, int K, int roundOut)
{
    extern __shared__ float sm[];
    float* sA = sm;
    float* sB = sm + 2 * GBUF;

    const int tid  = threadIdx.x;
    const int wid  = tid >> 5;
    const int lane = tid & 31;
    const int g    = lane >> 2;
    const int tg   = lane & 3;
    const int wm   = (wid & 3) * 32;
    const int wn   = (wid >> 2) * 64;
    const int m0 = blockIdx.y * 128;
    const int n0 = blockIdx.x * 128;

    const int lrow  = tid >> 1;
    const int lcol  = (tid & 1) * 16;
    const float* gA = A  + (size_t)(m0 + lrow) * K + lcol;
    const float* gB = BT + (size_t)(n0 + lrow) * K + lcol;
    const uint32_t sbase = smem_u32(sm);
    const uint32_t sArow = sbase + (uint32_t)(lrow * GPAD + lcol) * 4u;
    const uint32_t sBrow = sArow + 2u * GBUF * 4u;

    float acc[2][8][4];
#pragma unroll
    for (int mt = 0; mt < 2; mt++)
#pragma unroll
        for (int nt = 0; nt < 8; nt++)
#pragma unroll
            for (int i = 0; i < 4; i++) acc[mt][nt][i] = 0.f;

    const int nch = K >> 5;
    {
#pragma unroll
        for (int j = 0; j < 4; j++) {
            CP_ASYNC16(sArow + j * 16u, gA + j * 4);
            CP_ASYNC16(sBrow + j * 16u, gB + j * 4);
        }
        CP_COMMIT();
    }

    for (int c = 0; c < nch; ++c) {
        const int buf = c & 1;
        if (c + 1 < nch) {
            const uint32_t off = (uint32_t)(((c + 1) & 1) * GBUF) * 4u;
            const float* pa = gA + (c + 1) * 32;
            const float* pb = gB + (c + 1) * 32;
#pragma unroll
            for (int j = 0; j < 4; j++) {
                CP_ASYNC16(sArow + off + j * 16u, pa + j * 4);
                CP_ASYNC16(sBrow + off + j * 16u, pb + j * 4);
            }
            CP_COMMIT();
            CP_WAIT(1);
        } else {
            CP_WAIT(0);
        }
        __syncthreads();

        const float* tA = sA + buf * GBUF;
        const float* tB = sB + buf * GBUF;

#pragma unroll
        for (int ks = 0; ks < 4; ++ks) {
            const int kk = ks * 8 + tg;
            uint32_t af[2][4];
#pragma unroll
            for (int mt = 0; mt < 2; mt++) {
                const int r = wm + mt * 16 + g;
                af[mt][0] = __float_as_uint(tA[r * GPAD + kk]);
                af[mt][1] = __float_as_uint(tA[(r + 8) * GPAD + kk]);
                af[mt][2] = __float_as_uint(tA[r * GPAD + kk + 4]);
                af[mt][3] = __float_as_uint(tA[(r + 8) * GPAD + kk + 4]);
            }
            uint32_t bf[8][2];
#pragma unroll
            for (int nt = 0; nt < 8; nt++) {
                const int r = wn + nt * 8 + g;
                bf[nt][0] = __float_as_uint(tB[r * GPAD + kk]);
                bf[nt][1] = __float_as_uint(tB[r * GPAD + kk + 4]);
            }
#pragma unroll
            for (int mt = 0; mt < 2; mt++)
#pragma unroll
                for (int nt = 0; nt < 8; nt++)
                    mma_tf32_16x8x8(acc[mt][nt][0], acc[mt][nt][1],
                                    acc[mt][nt][2], acc[mt][nt][3],
                                    af[mt][0], af[mt][1], af[mt][2], af[mt][3],
                                    bf[nt][0], bf[nt][1]);
        }
        __syncthreads();
    }

#pragma unroll
    for (int mt = 0; mt < 2; mt++) {
        const int r0 = m0 + wm + mt * 16 + g;
#pragma unroll
        for (int nt = 0; nt < 8; nt++) {
            const int col = n0 + wn + nt * 8 + 2 * tg;
            float2 v0 = make_float2(acc[mt][nt][0], acc[mt][nt][1]);
            float2 v1 = make_float2(acc[mt][nt][2], acc[mt][nt][3]);
            if (roundOut) {
                v0.x = f2tf32f(v0.x); v0.y = f2tf32f(v0.y);
                v1.x = f2tf32f(v1.x); v1.y = f2tf32f(v1.y);
            }
            *(float2*)(C + (size_t)r0 * N + col) = v0;
            *(float2*)(C + (size_t)(r0 + 8) * N + col) = v1;
        }
    }
}

// ---------------- fused RMSNorm + RoPE (q + k in one launch) ------------------
__global__ __launch_bounds__(256)
void norm_rope_all(float* __restrict__ qkv, const float* __restrict__ qw,
                   const float* __restrict__ kw, const int* __restrict__ pos)
{
    const int bx = blockIdx.x;
    float* x; const float* w; int nheads; float scale; int lb;
    if (bx < 8192) { x = qkv;       w = qw; nheads = NH;  scale = 0.125f; lb = bx; }
    else           { x = qkv + HID; w = kw; nheads = NKV; scale = 1.0f;   lb = bx - 8192; }

    const int gw = (lb * 256 + (int)threadIdx.x) >> 5;
    const int lane = threadIdx.x & 31;
    const int s = gw / nheads;
    const int hh = gw - s * nheads;

    float* p = x + (size_t)s * QKVW + hh * HD;
    float x0 = p[lane];
    float x1 = p[lane + 32];

    float ss = x0 * x0 + x1 * x1;
#pragma unroll
    for (int o = 16; o; o >>= 1) ss += __shfl_xor_sync(0xffffffffu, ss, o);
    const float inv = rsqrtf(ss * (1.f / 64.f) + 1e-6f);
    x0 *= inv * w[lane];
    x1 *= inv * w[lane + 32];

    const float ang = (float)pos[s] * __expf(-(float)lane * (1.f / 32.f) * 9.2103403719761836f);
    float sn, c;
    sincosf(ang, &sn, &c);
    p[lane]      = f2tf32f((x0 * c - x1 * sn) * scale);
    p[lane + 32] = f2tf32f((x1 * c + x0 * sn) * scale);
}

// ---------------- causal flash attention --------------------------------------
// __launch_bounds__(256, 2): force <=128 regs so 2 blocks/SM (occ 25%).
// ld strides are compile-time (QKVW) to cut register pressure.
#define APAD 68
#define KVTILE (64 * APAD)
#define AT_SMEM_FLOATS (4 * KVTILE)
#define AT_SMEM_BYTES  (AT_SMEM_FLOATS * 4)    /* 69632 B */
#define L2E 1.4426950408889634f

__global__ __launch_bounds__(256, 2)
void attn_mma(const float* __restrict__ qb, const float* __restrict__ kb,
              const float* __restrict__ vb, float* __restrict__ ob)
{
    extern __shared__ float sm[];

    const int tid = threadIdx.x;
    const int wid = tid >> 5;
    const int lane = tid & 31;
    const int g = lane >> 2;
    const int tg = lane & 3;
    const int nqt = SEQ / 128;
    const int qt = nqt - 1 - ((int)blockIdx.x >> 5);
    const int h = (int)blockIdx.x & 31;
    const int kvh = h >> 2;
    const int dlim = 2 * wid + 2;

    const int lr = tid >> 2;
    const int lc4 = (tid & 3) * 16;
    const uint32_t sbase = smem_u32(sm);
    const uint32_t sKrow0 = sbase + (uint32_t)(lr * APAD + lc4) * 4u;
    const float* kbase = kb + (size_t)kvh * HD + lc4;
    const float* vbase = vb + (size_t)kvh * HD + lc4;

    // ---- Q fragments (pre-rounded, pre-scaled in gmem; stride QKVW const) ----
    uint32_t aq[8][4];
    {
        const float* qp = qb + (size_t)(qt * 128 + wid * 16) * QKVW + h * HD;
#pragma unroll
        for (int ks = 0; ks < 8; ks++) {
            const int c0 = ks * 8 + tg;
            aq[ks][0] = __float_as_uint(qp[(size_t)g * QKVW + c0]);
            aq[ks][1] = __float_as_uint(qp[(size_t)(g + 8) * QKVW + c0]);
            aq[ks][2] = __float_as_uint(qp[(size_t)g * QKVW + c0 + 4]);
            aq[ks][3] = __float_as_uint(qp[(size_t)(g + 8) * QKVW + c0 + 4]);
        }
    }

    float o[8][4];
#pragma unroll
    for (int nt = 0; nt < 8; nt++)
#pragma unroll
        for (int i = 0; i < 4; i++) o[nt][i] = 0.f;
    float m0 = -1e30f, m1 = -1e30f, l0 = 0.f, l1 = 0.f;

    const int r0g = qt * 128 + wid * 16 + g;
    const int r1g = r0g + 8;
    const int nkt = 2 * qt + 2;

    // ---- prefetch tile 0 ----
    {
        const float* kp = kbase + (size_t)lr * QKVW;
        const float* vp = vbase + (size_t)lr * QKVW;
#pragma unroll
        for (int j = 0; j < 4; j++) {
            CP_ASYNC16(sKrow0 + j * 16u, kp + j * 4);
            CP_ASYNC16(sKrow0 + (uint32_t)KVTILE * 4u + j * 16u, vp + j * 4);
        }
        CP_COMMIT();
    }

    for (int kt = 0; kt < nkt; ++kt) {
        if (kt + 1 < nkt) {
            const uint32_t boff = (uint32_t)(((kt + 1) & 1) * 2 * KVTILE) * 4u;
            const float* kp = kbase + (size_t)((kt + 1) * 64 + lr) * QKVW;
            const float* vp = vbase + (size_t)((kt + 1) * 64 + lr) * QKVW;
#pragma unroll
            for (int j = 0; j < 4; j++) {
                CP_ASYNC16(sKrow0 + boff + j * 16u, kp + j * 4);
                CP_ASYNC16(sKrow0 + boff + (uint32_t)KVTILE * 4u + j * 16u, vp + j * 4);
            }
            CP_COMMIT();
            CP_WAIT(1);
        } else {
            CP_WAIT(0);
        }
        __syncthreads();

        const float* Ks = sm + (kt & 1) * 2 * KVTILE;
        const float* Vs = Ks + KVTILE;

        const bool diag = (kt == 2 * qt);
        const bool active = !(kt == 2 * qt + 1 && wid < 4);
        if (active) {
            // ---- S = Q @ K^T ----
            float s[8][4];
#pragma unroll
            for (int nt = 0; nt < 8; nt++)
#pragma unroll
                for (int i = 0; i < 4; i++) s[nt][i] = 0.f;

#pragma unroll
            for (int ks = 0; ks < 8; ks++) {
                const int kk = ks * 8 + tg;
#pragma unroll
                for (int nt = 0; nt < 8; nt++) {
                    if (diag && nt >= dlim) continue;
                    const uint32_t b0 = __float_as_uint(Ks[(nt * 8 + g) * APAD + kk]);
                    const uint32_t b1 = __float_as_uint(Ks[(nt * 8 + g) * APAD + kk + 4]);
                    mma_tf32_16x8x8(s[nt][0], s[nt][1], s[nt][2], s[nt][3],
                                    aq[ks][0], aq[ks][1], aq[ks][2], aq[ks][3],
                                    b0, b1);
                }
            }

            // ---- causal mask ----
            if (kt >= 2 * qt) {
#pragma unroll
                for (int nt = 0; nt < 8; nt++) {
                    const int j0 = kt * 64 + nt * 8 + 2 * tg;
                    if (j0 > r0g)     s[nt][0] = -1e30f;
                    if (j0 + 1 > r0g) s[nt][1] = -1e30f;
                    if (j0 > r1g)     s[nt][2] = -1e30f;
                    if (j0 + 1 > r1g) s[nt][3] = -1e30f;
                }
            }

            // ---- online softmax ----
            float mx0 = -1e30f, mx1 = -1e30f;
#pragma unroll
            for (int nt = 0; nt < 8; nt++) {
                mx0 = fmaxf(mx0, fmaxf(s[nt][0], s[nt][1]));
                mx1 = fmaxf(mx1, fmaxf(s[nt][2], s[nt][3]));
            }
            mx0 = fmaxf(mx0, __shfl_xor_sync(0xffffffffu, mx0, 1));
            mx0 = fmaxf(mx0, __shfl_xor_sync(0xffffffffu, mx0, 2));
            mx1 = fmaxf(mx1, __shfl_xor_sync(0xffffffffu, mx1, 1));
            mx1 = fmaxf(mx1, __shfl_xor_sync(0xffffffffu, mx1, 2));

            const float mn0 = fmaxf(m0, mx0);
            const float mn1 = fmaxf(m1, mx1);
            const float al0 = ex2((m0 - mn0) * L2E);
            const float al1 = ex2((m1 - mn1) * L2E);
            float sum0 = 0.f, sum1 = 0.f;
#pragma unroll
            for (int nt = 0; nt < 8; nt++) {
                s[nt][0] = ex2((s[nt][0] - mn0) * L2E);
                s[nt][1] = ex2((s[nt][1] - mn0) * L2E);
                s[nt][2] = ex2((s[nt][2] - mn1) * L2E);
                s[nt][3] = ex2((s[nt][3] - mn1) * L2E);
                sum0 += s[nt][0] + s[nt][1];
                sum1 += s[nt][2] + s[nt][3];
            }
            sum0 += __shfl_xor_sync(0xffffffffu, sum0, 1);
            sum0 += __shfl_xor_sync(0xffffffffu, sum0, 2);
            sum1 += __shfl_xor_sync(0xffffffffu, sum1, 1);
            sum1 += __shfl_xor_sync(0xffffffffu, sum1, 2);
            m0 = mn0; m1 = mn1;
            l0 = l0 * al0 + sum0;
            l1 = l1 * al1 + sum1;
#pragma unroll
            for (int nt = 0; nt < 8; nt++) {
                o[nt][0] *= al0; o[nt][1] *= al0;
                o[nt][2] *= al1; o[nt][3] *= al1;
            }

            // ---- O += P @ V ----
            const int qbase = lane & ~3;
            const int s1 = qbase + (tg >> 1);
            const int s2 = s1 + 2;
            const bool odd = (tg & 1);
#pragma unroll
            for (int ks = 0; ks < 8; ks++) {
                if (diag && ks >= dlim) continue;
                const float v0 = __shfl_sync(0xffffffffu, s[ks][0], s1);
                const float v1 = __shfl_sync(0xffffffffu, s[ks][1], s1);
                const float v2 = __shfl_sync(0xffffffffu, s[ks][2], s1);
                const float v3 = __shfl_sync(0xffffffffu, s[ks][3], s1);
                const float w0 = __shfl_sync(0xffffffffu, s[ks][0], s2);
                const float w1 = __shfl_sync(0xffffffffu, s[ks][1], s2);
                const float w2 = __shfl_sync(0xffffffffu, s[ks][2], s2);
                const float w3 = __shfl_sync(0xffffffffu, s[ks][3], s2);
                const uint32_t a0 = f2tf32(odd ? v1 : v0);
                const uint32_t a1 = f2tf32(odd ? v3 : v2);
                const uint32_t a2 = f2tf32(odd ? w1 : w0);
                const uint32_t a3 = f2tf32(odd ? w3 : w2);
                const int kk = ks * 8 + tg;
#pragma unroll
                for (int nt = 0; nt < 8; nt++) {
                    const uint32_t b0 = __float_as_uint(Vs[kk * APAD + nt * 8 + g]);
                    const uint32_t b1 = __float_as_uint(Vs[(kk + 4) * APAD + nt * 8 + g]);
                    mma_tf32_16x8x8(o[nt][0], o[nt][1], o[nt][2], o[nt][3],
                                    a0, a1, a2, a3, b0, b1);
                }
            }
        }
        __syncthreads();
    }

    // ---- epilogue ----
    const float il0 = 1.f / l0;
    const float il1 = 1.f / l1;
#pragma unroll
    for (int nt = 0; nt < 8; nt++) {
        const int col = h * HD + nt * 8 + 2 * tg;
        *(float2*)(ob + (size_t)r0g * HID + col) =
            make_float2(f2tf32f(o[nt][0] * il0), f2tf32f(o[nt][1] * il0));
        *(float2*)(ob + (size_t)r1g * HID + col) =
            make_float2(f2tf32f(o[nt][2] * il1), f2tf32f(o[nt][3] * il1));
    }
}

// ---------------- launch ------------------------------------------------------
extern "C" void kernel_launch(void* const* d_in, const int* in_sizes, int n_in,
                              void* d_out, int out_size)
{
    const float* hs  = (const float*)d_in[0];
    const int*   pos = (const int*)  d_in[1];
    const float* wq  = (const float*)d_in[2];
    const float* wk  = (const float*)d_in[3];
    const float* wv  = (const float*)d_in[4];
    const float* wo  = (const float*)d_in[5];
    const float* qw  = (const float*)d_in[6];
    const float* kw  = (const float*)d_in[7];
    float* out = (float*)d_out;

    float *pqkv, *pa, *phs, *pwqkvT, *pwoT;
    cudaGetSymbolAddress((void**)&pqkv, g_qkv);
    cudaGetSymbolAddress((void**)&pa, g_att);
    cudaGetSymbolAddress((void**)&phs, g_hs32);
    cudaGetSymbolAddress((void**)&pwqkvT, g_wqkvT);
    cudaGetSymbolAddress((void**)&pwoT, g_woT);

    cudaFuncSetAttribute(gemm_mma, cudaFuncAttributeMaxDynamicSharedMemorySize,
                         G_SMEM_BYTES);
    cudaFuncSetAttribute(attn_mma, cudaFuncAttributeMaxDynamicSharedMemorySize,
                         AT_SMEM_BYTES);

    prep_kernel<<<14336, 256>>>(hs, wq, wk, wv, wo, phs, pwqkvT, pwoT);

    gemm_mma<<<dim3(QKVW / 128, SEQ / 128), 256, G_SMEM_BYTES>>>(phs, pwqkvT, pqkv, SEQ, QKVW, HID, 1);

    norm_rope_all<<<10240, 256>>>(pqkv, qw, kw, pos);

    float* pk = pqkv + HID;
    float* pv = pqkv + HID + KVW;
    attn_mma<<<512, 256, AT_SMEM_BYTES>>>(pqkv, pk, pv, pa);

    gemm_mma<<<dim3(HID / 128, SEQ / 128), 256, G_SMEM_BYTES>>>(pa, pwoT, out, SEQ, HID, HID, 0);
}

// round 13
// speedup vs baseline: 1.1528x; 1.0211x over previous
#include <cuda_runtime.h>
#include <math.h>
#include <stdint.h>

#define SEQ 2048
#define HID 2048
#define NH 32
#define NKV 8
#define HD 64
#define KVW (NKV*HD)       /* 512 */
#define QKVW (HID + 2*KVW) /* 3072 */

// ---------------- scratch ------------------------------------------------------
__device__ float g_qkv[SEQ * QKVW];
__device__ float g_att[SEQ * HID];
__device__ float g_hs32[SEQ * HID];
__device__ float g_wqkvT[QKVW * HID];
__device__ float g_woT[HID * HID];

// ================= helpers =================
__device__ __forceinline__ uint32_t smem_u32(const void* p) {
    uint32_t a;
    asm("{ .reg .u64 t; cvta.to.shared.u64 t, %1; cvt.u32.u64 %0, t; }" : "=r"(a) : "l"(p));
    return a;
}
__device__ __forceinline__ uint32_t f2tf32(float f) {
    uint32_t r;
    asm("cvt.rna.tf32.f32 %0, %1;" : "=r"(r) : "f"(f));
    return r;
}
__device__ __forceinline__ float f2tf32f(float f) {
    return __uint_as_float(f2tf32(f));
}
__device__ __forceinline__ float ex2(float x) {
    float r;
    asm("ex2.approx.ftz.f32 %0, %1;" : "=f"(r) : "f"(x));
    return r;
}
#define CP_ASYNC16(dst, src) \
    asm volatile("cp.async.cg.shared.global [%0], [%1], 16;" :: "r"(dst), "l"(src))
#define CP_COMMIT() asm volatile("cp.async.commit_group;" ::: "memory")
#define CP_WAIT(n)  asm volatile("cp.async.wait_group %0;" :: "n"(n) : "memory")

__device__ __forceinline__ void mma_tf32_16x8x8(float& c0, float& c1, float& c2, float& c3,
                                                uint32_t a0, uint32_t a1, uint32_t a2, uint32_t a3,
                                                uint32_t b0, uint32_t b1) {
    asm volatile(
        "mma.sync.aligned.m16n8k8.row.col.f32.tf32.tf32.f32 "
        "{%0,%1,%2,%3}, {%4,%5,%6,%7}, {%8,%9}, {%0,%1,%2,%3};"
        : "+f"(c0), "+f"(c1), "+f"(c2), "+f"(c3)
        : "r"(a0), "r"(a1), "r"(a2), "r"(a3), "r"(b0), "r"(b1));
}

// ---------------- fused prologue: round_copy + 4 weight transposes ------------
__global__ __launch_bounds__(256)
void prep_kernel(const float* __restrict__ hs, const float* __restrict__ wq,
                 const float* __restrict__ wk, const float* __restrict__ wv,
                 const float* __restrict__ wo,
                 float* __restrict__ hs32, float* __restrict__ wqkvT,
                 float* __restrict__ woT)
{
    const int bx = blockIdx.x;
    const int tid = threadIdx.x;

    if (bx < 4096) {
        const int i = (bx * 256 + tid) * 4;
        float4 v = *(const float4*)(hs + i);
        v.x = f2tf32f(v.x); v.y = f2tf32f(v.y);
        v.z = f2tf32f(v.z); v.w = f2tf32f(v.w);
        *(float4*)(hs32 + i) = v;
        return;
    }

    __shared__ float t[32][33];
    const int tx = tid & 31;
    const int ty = tid >> 5;
    const float* in;
    float* out;
    int N, lb;
    if (bx < 8192)       { in = wq; out = wqkvT;                          N = HID; lb = bx - 4096; }
    else if (bx < 9216)  { in = wk; out = wqkvT + (size_t)HID * HID;      N = KVW; lb = bx - 8192; }
    else if (bx < 10240) { in = wv; out = wqkvT + (size_t)(HID+KVW)*HID;  N = KVW; lb = bx - 9216; }
    else                 { in = wo; out = woT;                            N = HID; lb = bx - 10240; }
    const int gw = N / 32;
    const int bxx = (lb % gw) * 32;
    const int byy = (lb / gw) * 32;
#pragma unroll
    for (int i = 0; i < 32; i += 8)
        t[ty + i][tx] = in[(size_t)(byy + ty + i) * N + bxx + tx];
    __syncthreads();
#pragma unroll
    for (int i = 0; i < 32; i += 8)
        out[(size_t)(bxx + ty + i) * HID + byy + tx] = f2tf32f(t[tx][ty + i]);
}

// ---------------- tf32 mma.sync GEMM ------------------------------------------
#define GPAD 36
#define GBUF (128 * GPAD)
#define G_SMEM_BYTES (4 * GBUF * 4)

__global__ __launch_bounds__(256)
void gemm_mma(const float* __restrict__ A, const float* __restrict__ BT,
              float* __restrict__ C, int M, int N, int K, int roundOut)
{
    extern __shared__ float sm[];
    float* sA = sm;
    float* sB = sm + 2 * GBUF;

    const int tid  = threadIdx.x;
    const int wid  = tid >> 5;
    const int lane = tid & 31;
    const int g    = lane >> 2;
    const int tg   = lane & 3;
    const int wm   = (wid & 3) * 32;
    const int wn   = (wid >> 2) * 64;
    const int m0 = blockIdx.y * 128;
    const int n0 = blockIdx.x * 128;

    const int lrow  = tid >> 1;
    const int lcol  = (tid & 1) * 16;
    const float* gA = A  + (size_t)(m0 + lrow) * K + lcol;
    const float* gB = BT + (size_t)(n0 + lrow) * K + lcol;
    const uint32_t sbase = smem_u32(sm);
    const uint32_t sArow = sbase + (uint32_t)(lrow * GPAD + lcol) * 4u;
    const uint32_t sBrow = sArow + 2u * GBUF * 4u;

    float acc[2][8][4];
#pragma unroll
    for (int mt = 0; mt < 2; mt++)
#pragma unroll
        for (int nt = 0; nt < 8; nt++)
#pragma unroll
            for (int i = 0; i < 4; i++) acc[mt][nt][i] = 0.f;

    const int nch = K >> 5;
    {
#pragma unroll
        for (int j = 0; j < 4; j++) {
            CP_ASYNC16(sArow + j * 16u, gA + j * 4);
            CP_ASYNC16(sBrow + j * 16u, gB + j * 4);
        }
        CP_COMMIT();
    }

    for (int c = 0; c < nch; ++c) {
        const int buf = c & 1;
        if (c + 1 < nch) {
            const uint32_t off = (uint32_t)(((c + 1) & 1) * GBUF) * 4u;
            const float* pa = gA + (c + 1) * 32;
            const float* pb = gB + (c + 1) * 32;
#pragma unroll
            for (int j = 0; j < 4; j++) {
                CP_ASYNC16(sArow + off + j * 16u, pa + j * 4);
                CP_ASYNC16(sBrow + off + j * 16u, pb + j * 4);
            }
            CP_COMMIT();
            CP_WAIT(1);
        } else {
            CP_WAIT(0);
        }
        __syncthreads();

        const float* tA = sA + buf * GBUF;
        const float* tB = sB + buf * GBUF;

#pragma unroll
        for (int ks = 0; ks < 4; ++ks) {
            const int kk = ks * 8 + tg;
            uint32_t af[2][4];
#pragma unroll
            for (int mt = 0; mt < 2; mt++) {
                const int r = wm + mt * 16 + g;
                af[mt][0] = __float_as_uint(tA[r * GPAD + kk]);
                af[mt][1] = __float_as_uint(tA[(r + 8) * GPAD + kk]);
                af[mt][2] = __float_as_uint(tA[r * GPAD + kk + 4]);
                af[mt][3] = __float_as_uint(tA[(r + 8) * GPAD + kk + 4]);
            }
            uint32_t bf[8][2];
#pragma unroll
            for (int nt = 0; nt < 8; nt++) {
                const int r = wn + nt * 8 + g;
                bf[nt][0] = __float_as_uint(tB[r * GPAD + kk]);
                bf[nt][1] = __float_as_uint(tB[r * GPAD + kk + 4]);
            }
#pragma unroll
            for (int mt = 0; mt < 2; mt++)
#pragma unroll
                for (int nt = 0; nt < 8; nt++)
                    mma_tf32_16x8x8(acc[mt][nt][0], acc[mt][nt][1],
                                    acc[mt][nt][2], acc[mt][nt][3],
                                    af[mt][0], af[mt][1], af[mt][2], af[mt][3],
                                    bf[nt][0], bf[nt][1]);
        }
        __syncthreads();
    }

#pragma unroll
    for (int mt = 0; mt < 2; mt++) {
        const int r0 = m0 + wm + mt * 16 + g;
#pragma unroll
        for (int nt = 0; nt < 8; nt++) {
            const int col = n0 + wn + nt * 8 + 2 * tg;
            float2 v0 = make_float2(acc[mt][nt][0], acc[mt][nt][1]);
            float2 v1 = make_float2(acc[mt][nt][2], acc[mt][nt][3]);
            if (roundOut) {
                v0.x = f2tf32f(v0.x); v0.y = f2tf32f(v0.y);
                v1.x = f2tf32f(v1.x); v1.y = f2tf32f(v1.y);
            }
            *(float2*)(C + (size_t)r0 * N + col) = v0;
            *(float2*)(C + (size_t)(r0 + 8) * N + col) = v1;
        }
    }
}

// ---------------- fused RMSNorm + RoPE (q + k in one launch) ------------------
__global__ __launch_bounds__(256)
void norm_rope_all(float* __restrict__ qkv, const float* __restrict__ qw,
                   const float* __restrict__ kw, const int* __restrict__ pos)
{
    const int bx = blockIdx.x;
    float* x; const float* w; int nheads; float scale; int lb;
    if (bx < 8192) { x = qkv;       w = qw; nheads = NH;  scale = 0.125f; lb = bx; }
    else           { x = qkv + HID; w = kw; nheads = NKV; scale = 1.0f;   lb = bx - 8192; }

    const int gw = (lb * 256 + (int)threadIdx.x) >> 5;
    const int lane = threadIdx.x & 31;
    const int s = gw / nheads;
    const int hh = gw - s * nheads;

    float* p = x + (size_t)s * QKVW + hh * HD;
    float x0 = p[lane];
    float x1 = p[lane + 32];

    float ss = x0 * x0 + x1 * x1;
#pragma unroll
    for (int o = 16; o; o >>= 1) ss += __shfl_xor_sync(0xffffffffu, ss, o);
    const float inv = rsqrtf(ss * (1.f / 64.f) + 1e-6f);
    x0 *= inv * w[lane];
    x1 *= inv * w[lane + 32];

    const float ang = (float)pos[s] * __expf(-(float)lane * (1.f / 32.f) * 9.2103403719761836f);
    float sn, c;
    sincosf(ang, &sn, &c);
    p[lane]      = f2tf32f((x0 * c - x1 * sn) * scale);
    p[lane + 32] = f2tf32f((x1 * c + x0 * sn) * scale);
}

// ---------------- causal flash attention --------------------------------------
// K tiles stride 68 (conflict-free for QK B-loads); V tiles stride 72
// (72 mod 32 = 8 -> PV B-load banks 8*tg+g all distinct: conflict-free).
#define KPAD 68
#define VPAD 72
#define KTILE (64 * KPAD)                       /* 4352 floats */
#define VTILE (64 * VPAD)                       /* 4608 floats */
#define AT_SMEM_FLOATS (2 * KTILE + 2 * VTILE)  /* 17920 floats */
#define AT_SMEM_BYTES  (AT_SMEM_FLOATS * 4)     /* 71680 B */
#define L2E 1.4426950408889634f

__global__ __launch_bounds__(256, 2)
void attn_mma(const float* __restrict__ qb, const float* __restrict__ kb,
              const float* __restrict__ vb, float* __restrict__ ob)
{
    extern __shared__ float sm[];
    // layout: [Ks0, Ks1, Vs0, Vs1]

    const int tid = threadIdx.x;
    const int wid = tid >> 5;
    const int lane = tid & 31;
    const int g = lane >> 2;
    const int tg = lane & 3;
    const int nqt = SEQ / 128;
    const int qt = nqt - 1 - ((int)blockIdx.x >> 5);
    const int h = (int)blockIdx.x & 31;
    const int kvh = h >> 2;
    const int dlim = 2 * wid + 2;

    const int lr = tid >> 2;
    const int lc4 = (tid & 3) * 16;
    const uint32_t sbase = smem_u32(sm);
    const uint32_t sKrow = sbase + (uint32_t)(lr * KPAD + lc4) * 4u;
    const uint32_t sVrow = sbase + (uint32_t)(2 * KTILE + lr * VPAD + lc4) * 4u;
    const float* kbase = kb + (size_t)kvh * HD + lc4;
    const float* vbase = vb + (size_t)kvh * HD + lc4;

    // ---- Q fragments (pre-rounded, pre-scaled in gmem) ----
    uint32_t aq[8][4];
    {
        const float* qp = qb + (size_t)(qt * 128 + wid * 16) * QKVW + h * HD;
#pragma unroll
        for (int ks = 0; ks < 8; ks++) {
            const int c0 = ks * 8 + tg;
            aq[ks][0] = __float_as_uint(qp[(size_t)g * QKVW + c0]);
            aq[ks][1] = __float_as_uint(qp[(size_t)(g + 8) * QKVW + c0]);
            aq[ks][2] = __float_as_uint(qp[(size_t)g * QKVW + c0 + 4]);
            aq[ks][3] = __float_as_uint(qp[(size_t)(g + 8) * QKVW + c0 + 4]);
        }
    }

    float o[8][4];
#pragma unroll
    for (int nt = 0; nt < 8; nt++)
#pragma unroll
        for (int i = 0; i < 4; i++) o[nt][i] = 0.f;
    float m0 = -1e30f, m1 = -1e30f, l0 = 0.f, l1 = 0.f;

    const int r0g = qt * 128 + wid * 16 + g;
    const int r1g = r0g + 8;
    const int nkt = 2 * qt + 2;

    // ---- prefetch tile 0 ----
    {
        const float* kp = kbase + (size_t)lr * QKVW;
        const float* vp = vbase + (size_t)lr * QKVW;
#pragma unroll
        for (int j = 0; j < 4; j++) {
            CP_ASYNC16(sKrow + j * 16u, kp + j * 4);
            CP_ASYNC16(sVrow + j * 16u, vp + j * 4);
        }
        CP_COMMIT();
    }

    for (int kt = 0; kt < nkt; ++kt) {
        if (kt + 1 < nkt) {
            const uint32_t kb_off = (uint32_t)(((kt + 1) & 1) * KTILE) * 4u;
            const uint32_t vb_off = (uint32_t)(((kt + 1) & 1) * VTILE) * 4u;
            const float* kp = kbase + (size_t)((kt + 1) * 64 + lr) * QKVW;
            const float* vp = vbase + (size_t)((kt + 1) * 64 + lr) * QKVW;
#pragma unroll
            for (int j = 0; j < 4; j++) {
                CP_ASYNC16(sKrow + kb_off + j * 16u, kp + j * 4);
                CP_ASYNC16(sVrow + vb_off + j * 16u, vp + j * 4);
            }
            CP_COMMIT();
            CP_WAIT(1);
        } else {
            CP_WAIT(0);
        }
        __syncthreads();

        const float* Ks = sm + (kt & 1) * KTILE;
        const float* Vs = sm + 2 * KTILE + (kt & 1) * VTILE;

        const bool diag = (kt == 2 * qt);
        const bool active = !(kt == 2 * qt + 1 && wid < 4);
        if (active) {
            // ---- S = Q @ K^T ----
            float s[8][4];
#pragma unroll
            for (int nt = 0; nt < 8; nt++)
#pragma unroll
                for (int i = 0; i < 4; i++) s[nt][i] = 0.f;

#pragma unroll
            for (int ks = 0; ks < 8; ks++) {
                const int kk = ks * 8 + tg;
#pragma unroll
                for (int nt = 0; nt < 8; nt++) {
                    if (diag && nt >= dlim) continue;
                    const uint32_t b0 = __float_as_uint(Ks[(nt * 8 + g) * KPAD + kk]);
                    const uint32_t b1 = __float_as_uint(Ks[(nt * 8 + g) * KPAD + kk + 4]);
                    mma_tf32_16x8x8(s[nt][0], s[nt][1], s[nt][2], s[nt][3],
                                    aq[ks][0], aq[ks][1], aq[ks][2], aq[ks][3],
                                    b0, b1);
                }
            }

            // ---- causal mask ----
            if (kt >= 2 * qt) {
#pragma unroll
                for (int nt = 0; nt < 8; nt++) {
                    const int j0 = kt * 64 + nt * 8 + 2 * tg;
                    if (j0 > r0g)     s[nt][0] = -1e30f;
                    if (j0 + 1 > r0g) s[nt][1] = -1e30f;
                    if (j0 > r1g)     s[nt][2] = -1e30f;
                    if (j0 + 1 > r1g) s[nt][3] = -1e30f;
                }
            }

            // ---- online softmax ----
            float mx0 = -1e30f, mx1 = -1e30f;
#pragma unroll
            for (int nt = 0; nt < 8; nt++) {
                mx0 = fmaxf(mx0, fmaxf(s[nt][0], s[nt][1]));
                mx1 = fmaxf(mx1, fmaxf(s[nt][2], s[nt][3]));
            }
            mx0 = fmaxf(mx0, __shfl_xor_sync(0xffffffffu, mx0, 1));
            mx0 = fmaxf(mx0, __shfl_xor_sync(0xffffffffu, mx0, 2));
            mx1 = fmaxf(mx1, __shfl_xor_sync(0xffffffffu, mx1, 1));
            mx1 = fmaxf(mx1, __shfl_xor_sync(0xffffffffu, mx1, 2));

            const float mn0 = fmaxf(m0, mx0);
            const float mn1 = fmaxf(m1, mx1);
            const float al0 = ex2((m0 - mn0) * L2E);
            const float al1 = ex2((m1 - mn1) * L2E);
            float sum0 = 0.f, sum1 = 0.f;
#pragma unroll
            for (int nt = 0; nt < 8; nt++) {
                s[nt][0] = ex2((s[nt][0] - mn0) * L2E);
                s[nt][1] = ex2((s[nt][1] - mn0) * L2E);
                s[nt][2] = ex2((s[nt][2] - mn1) * L2E);
                s[nt][3] = ex2((s[nt][3] - mn1) * L2E);
                sum0 += s[nt][0] + s[nt][1];
                sum1 += s[nt][2] + s[nt][3];
            }
            sum0 += __shfl_xor_sync(0xffffffffu, sum0, 1);
            sum0 += __shfl_xor_sync(0xffffffffu, sum0, 2);
            sum1 += __shfl_xor_sync(0xffffffffu, sum1, 1);
            sum1 += __shfl_xor_sync(0xffffffffu, sum1, 2);
            m0 = mn0; m1 = mn1;
            l0 = l0 * al0 + sum0;
            l1 = l1 * al1 + sum1;
#pragma unroll
            for (int nt = 0; nt < 8; nt++) {
                o[nt][0] *= al0; o[nt][1] *= al0;
                o[nt][2] *= al1; o[nt][3] *= al1;
            }

            // ---- O += P @ V (A-frags via quad shuffles; conflict-free V) ----
            const int qbase = lane & ~3;
            const int s1 = qbase + (tg >> 1);
            const int s2 = s1 + 2;
            const bool odd = (tg & 1);
#pragma unroll
            for (int ks = 0; ks < 8; ks++) {
                if (diag && ks >= dlim) continue;
                const float v0 = __shfl_sync(0xffffffffu, s[ks][0], s1);
                const float v1 = __shfl_sync(0xffffffffu, s[ks][1], s1);
                const float v2 = __shfl_sync(0xffffffffu, s[ks][2], s1);
                const float v3 = __shfl_sync(0xffffffffu, s[ks][3], s1);
                const float w0 = __shfl_sync(0xffffffffu, s[ks][0], s2);
                const float w1 = __shfl_sync(0xffffffffu, s[ks][1], s2);
                const float w2 = __shfl_sync(0xffffffffu, s[ks][2], s2);
                const float w3 = __shfl_sync(0xffffffffu, s[ks][3], s2);
                const uint32_t a0 = f2tf32(odd ? v1 : v0);
                const uint32_t a1 = f2tf32(odd ? v3 : v2);
                const uint32_t a2 = f2tf32(odd ? w1 : w0);
                const uint32_t a3 = f2tf32(odd ? w3 : w2);
                const int kk = ks * 8 + tg;
#pragma unroll
                for (int nt = 0; nt < 8; nt++) {
                    const uint32_t b0 = __float_as_uint(Vs[kk * VPAD + nt * 8 + g]);
                    const uint32_t b1 = __float_as_uint(Vs[(kk + 4) * VPAD + nt * 8 + g]);
                    mma_tf32_16x8x8(o[nt][0], o[nt][1], o[nt][2], o[nt][3],
                                    a0, a1, a2, a3, b0, b1);
                }
            }
        }
        __syncthreads();
    }

    // ---- epilogue ----
    const float il0 = 1.f / l0;
    const float il1 = 1.f / l1;
#pragma unroll
    for (int nt = 0; nt < 8; nt++) {
        const int col = h * HD + nt * 8 + 2 * tg;
        *(float2*)(ob + (size_t)r0g * HID + col) =
            make_float2(f2tf32f(o[nt][0] * il0), f2tf32f(o[nt][1] * il0));
        *(float2*)(ob + (size_t)r1g * HID + col) =
            make_float2(f2tf32f(o[nt][2] * il1), f2tf32f(o[nt][3] * il1));
    }
}

// ---------------- launch ------------------------------------------------------
extern "C" void kernel_launch(void* const* d_in, const int* in_sizes, int n_in,
                              void* d_out, int out_size)
{
    const float* hs  = (const float*)d_in[0];
    const int*   pos = (const int*)  d_in[1];
    const float* wq  = (const float*)d_in[2];
    const float* wk  = (const float*)d_in[3];
    const float* wv  = (const float*)d_in[4];
    const float* wo  = (const float*)d_in[5];
    const float* qw  = (const float*)d_in[6];
    const float* kw  = (const float*)d_in[7];
    float* out = (float*)d_out;

    float *pqkv, *pa, *phs, *pwqkvT, *pwoT;
    cudaGetSymbolAddress((void**)&pqkv, g_qkv);
    cudaGetSymbolAddress((void**)&pa, g_att);
    cudaGetSymbolAddress((void**)&phs, g_hs32);
    cudaGetSymbolAddress((void**)&pwqkvT, g_wqkvT);
    cudaGetSymbolAddress((void**)&pwoT, g_woT);

    cudaFuncSetAttribute(gemm_mma, cudaFuncAttributeMaxDynamicSharedMemorySize,
                         G_SMEM_BYTES);
    cudaFuncSetAttribute(attn_mma, cudaFuncAttributeMaxDynamicSharedMemorySize,
                         AT_SMEM_BYTES);

    prep_kernel<<<14336, 256>>>(hs, wq, wk, wv, wo, phs, pwqkvT, pwoT);

    gemm_mma<<<dim3(QKVW / 128, SEQ / 128), 256, G_SMEM_BYTES>>>(phs, pwqkvT, pqkv, SEQ, QKVW, HID, 1);

    norm_rope_all<<<10240, 256>>>(pqkv, qw, kw, pos);

    float* pk = pqkv + HID;
    float* pv = pqkv + HID + KVW;
    attn_mma<<<512, 256, AT_SMEM_BYTES>>>(pqkv, pk, pv, pa);

    gemm_mma<<<dim3(HID / 128, SEQ / 128), 256, G_SMEM_BYTES>>>(pa, pwoT, out, SEQ, HID, HID, 0);
}